// round 1
// baseline (speedup 1.0000x reference)
#include <cuda_runtime.h>
#include <math.h>

#define BB 512
#define TT 200
#define NTOK (BB*TT)          // 102400
#define CCLS 200
#define MIDQ 132              // (64+200)/2, also la hidden
#define NOUTS (BB*(TT-1))     // 101888

// ---------------- scratch (device globals; no allocation) ----------------
__device__ float g_HQ[NTOK*MIDQ];    // relu(qd_W1 @ qe)
__device__ float g_X [NTOK*320];     // GRU input features
__device__ float g_XP[NTOK*192];     // W_ih @ x + b_ih
__device__ float g_HS[NTOK*64];      // GRU hidden states
__device__ float g_HL[NTOK*MIDQ];    // relu(la_W1 @ h)
__device__ float g_disc[NTOK];
__device__ float g_Sqd[NTOK];
__device__ int4  g_cls[NTOK];        // deduped class ids (-1 = skip)

__device__ __forceinline__ float sigmoidf_(float x){ return 1.f/(1.f+expf(-x)); }

// ---------------- K1/K5: out[n,132] = relu(W(132x64) @ rows[idx[n]] + b) ----
__global__ void hidden132_kernel(const float* __restrict__ W, const float* __restrict__ bias,
                                 const float* __restrict__ rows, const int* __restrict__ idx,
                                 float* __restrict__ out)
{
    __shared__ float4 tile[128][16];    // 128 tokens x 64 floats
    int tid = threadIdx.x;
    float w[64]; float bv = 0.f;
    if (tid < MIDQ) {
        #pragma unroll
        for (int k = 0; k < 64; k++) w[k] = W[tid*64 + k];
        bv = bias[tid];
    }
    int tok0 = blockIdx.x * 128;
    for (int i = tid; i < 128*16; i += blockDim.x) {
        int r = i >> 4, c = i & 15;
        int tok = tok0 + r;
        int row = idx ? idx[tok] : tok;
        tile[r][c] = reinterpret_cast<const float4*>(rows + (size_t)row*64)[c];
    }
    __syncthreads();
    if (tid < MIDQ) {
        for (int r = 0; r < 128; r++) {
            float acc = bv;
            #pragma unroll
            for (int c = 0; c < 16; c++) {
                float4 v = tile[r][c];
                acc = fmaf(w[4*c+0], v.x, acc);
                acc = fmaf(w[4*c+1], v.y, acc);
                acc = fmaf(w[4*c+2], v.z, acc);
                acc = fmaf(w[4*c+3], v.w, acc);
            }
            out[(size_t)(tok0+r)*MIDQ + tid] = fmaxf(acc, 0.f);
        }
    }
}

// ---------------- K2: per-token features -> X rows + disc/Sqd/cls ----------
__global__ void features_kernel(
  const float* __restrict__ E_q, const float* __restrict__ E_c,
  const float* __restrict__ E_it, const float* __restrict__ E_ut, const float* __restrict__ E_nh,
  const float* __restrict__ W_fuse, const float* __restrict__ b_fuse,
  const float* __restrict__ qd_W2, const float* __restrict__ qd_b2,
  const float* __restrict__ dc_W1, const float* __restrict__ dc_b1,
  const float* __restrict__ dc_W2, const float* __restrict__ dc_b2,
  const int* __restrict__ qseq, const int* __restrict__ cseq,
  const int* __restrict__ itseq, const int* __restrict__ utseq,
  const int* __restrict__ nhseq, const int* __restrict__ naseq,
  const int* __restrict__ q2c, const int* __restrict__ q2cm)
{
  extern __shared__ float Wf[];            // [64][193] padded, row-major: Wf[r*193+k]
  __shared__ float dc1[64*32];             // k-major: dc1[k*32+l]
  __shared__ float dc2s[32], dcb1s[32], bfs[64];
  __shared__ float dcb2s;
  __shared__ int qv[64], cv[64], itv[64], utv[64], nhv[64], nav[64];
  __shared__ float qe_s[64], eit_s[64], utn_s[192], hq_s[MIDQ], f_s[64];
  __shared__ float qdv_s[4], rel_s[4], srel_s;
  __shared__ int cls_s[4], msk_s[4];

  int tid = threadIdx.x;
  int n0 = blockIdx.x * 64;
  // stage weights (coalesced global reads, conflict-free smem writes)
  for (int i = tid; i < 64*192; i += 128) { int r = i/192, k = i%192; Wf[r*193+k] = W_fuse[i]; }
  for (int i = tid; i < 32*64;  i += 128) { int l = i/64,  k = i%64;  dc1[k*32+l] = dc_W1[i]; }
  if (tid < 32) { dc2s[tid] = dc_W2[tid]; dcb1s[tid] = dc_b1[tid]; }
  if (tid < 64) {
    bfs[tid] = b_fuse[tid];
    qv[tid]  = qseq [n0+tid]; cv[tid]  = cseq [n0+tid]; itv[tid] = itseq[n0+tid];
    utv[tid] = utseq[n0+tid]; nhv[tid] = nhseq[n0+tid]; nav[tid] = naseq[n0+tid];
  }
  if (tid == 0) dcb2s = dc_b2[0];
  __syncthreads();

  int lane = tid & 31, wid = tid >> 5;

  for (int tl = 0; tl < 64; tl++) {
    int n = n0 + tl;
    int q = qv[tl];
    // gather inputs
    if (tid < 64) { qe_s[tid] = E_q[q*64+tid]; eit_s[tid] = E_it[itv[tl]*64+tid]; }
    if (tid < 128) utn_s[tid] = (tid < 64) ? E_ut[utv[tl]*64+tid] : E_nh[nhv[tl]*64+tid-64];
    if (tid < 64)  utn_s[128+tid] = E_nh[nav[tl]*64+tid];
    if (tid < 128) hq_s[tid] = g_HQ[(size_t)n*MIDQ + tid];
    if (tid < 4)   hq_s[128+tid] = g_HQ[(size_t)n*MIDQ + 128 + tid];
    __syncthreads();

    // qd at 4 candidate classes (one warp per class)
    {
      int c = q2c[q*4+wid]; int m = q2cm[q*4+wid];
      float acc = 0.f;
      for (int k = lane; k < MIDQ; k += 32) acc += qd_W2[c*MIDQ+k]*hq_s[k];
      #pragma unroll
      for (int o = 16; o > 0; o >>= 1) acc += __shfl_xor_sync(0xffffffffu, acc, o);
      if (lane == 0) {
        float qd = sigmoidf_(acc + qd_b2[c]);
        qdv_s[wid] = qd; rel_s[wid] = qd*(float)m; cls_s[wid] = c; msk_s[wid] = m;
      }
    }
    __syncthreads();

    if (wid == 0) {               // discrimination MLP
      float acc = dcb1s[lane];
      #pragma unroll 8
      for (int k = 0; k < 64; k++) acc += dc1[k*32+lane]*qe_s[k];
      float v = dc2s[lane]*fmaxf(acc, 0.f);
      #pragma unroll
      for (int o = 16; o > 0; o >>= 1) v += __shfl_xor_sync(0xffffffffu, v, o);
      if (lane == 0) g_disc[n] = sigmoidf_(v + dcb2s)*10.f;
    } else if (tid == 32) {       // srel + dedup (Q_table indicator equivalent)
      srel_s = rel_s[0]+rel_s[1]+rel_s[2]+rel_s[3]+1e-6f;
      float S = 0.f; int cl[4];
      #pragma unroll
      for (int j = 0; j < 4; j++) {
        int c = cls_s[j]; bool fl = (msk_s[j] != 0);
        for (int j2 = 0; j2 < j; j2++) if (msk_s[j2] != 0 && cls_s[j2] == c) fl = false;
        if (fl) { S += qdv_s[j]; cl[j] = c; } else cl[j] = -1;
      }
      g_Sqd[n] = S;
      g_cls[n] = make_int4(cl[0], cl[1], cl[2], cl[3]);
    } else if (wid >= 2) {        // fuse = W_fuse @ utn + b_fuse
      int rr = tid - 64;
      float f = bfs[rr];
      #pragma unroll 8
      for (int k = 0; k < 192; k++) f += Wf[rr*193+k]*utn_s[k];
      f_s[rr] = f;
    }
    __syncthreads();

    if (tid < 64) {
      float ce = rel_s[0]*E_c[cls_s[0]*64+tid] + rel_s[1]*E_c[cls_s[1]*64+tid]
               + rel_s[2]*E_c[cls_s[2]*64+tid] + rel_s[3]*E_c[cls_s[3]*64+tid];
      ce /= srel_s;
      size_t base = (size_t)n*320;
      g_X[base       + tid] = qe_s[tid];
      g_X[base +  64 + tid] = ce;
      g_X[base + 128 + tid] = (float)cv[tl];
      g_X[base + 192 + tid] = eit_s[tid];
      g_X[base + 256 + tid] = f_s[tid];
    }
    __syncthreads();
  }
}

// ---------------- K3: XP = X(102400x320) @ W_ih^T(320x192) + b --------------
__global__ void xp_gemm_kernel(const float* __restrict__ W_ih, const float* __restrict__ b_ih)
{
  __shared__ float Xs[32*65];    // [k][m], padded
  __shared__ float Ws[32*193];   // [k][n], padded
  int tid = threadIdx.x;
  int tx = tid & 15, ty = tid >> 4;
  int m0 = blockIdx.x * 64;
  float acc[4][12];
  #pragma unroll
  for (int p = 0; p < 4; p++)
    #pragma unroll
    for (int u = 0; u < 12; u++) acc[p][u] = 0.f;

  for (int kb = 0; kb < 320; kb += 32) {
    for (int i = tid; i < 64*32; i += 256) {
      int m = i >> 5, kk = i & 31;
      Xs[kk*65+m] = g_X[(size_t)(m0+m)*320 + kb + kk];
    }
    for (int i = tid; i < 192*32; i += 256) {
      int nn = i >> 5, kk = i & 31;
      Ws[kk*193+nn] = W_ih[nn*320 + kb + kk];
    }
    __syncthreads();
    #pragma unroll
    for (int kk = 0; kk < 32; kk++) {
      float a[4], bb[12];
      #pragma unroll
      for (int p = 0; p < 4; p++) a[p] = Xs[kk*65 + ty*4 + p];
      #pragma unroll
      for (int u = 0; u < 12; u++) bb[u] = Ws[kk*193 + tx*12 + u];
      #pragma unroll
      for (int p = 0; p < 4; p++)
        #pragma unroll
        for (int u = 0; u < 12; u++) acc[p][u] = fmaf(a[p], bb[u], acc[p][u]);
    }
    __syncthreads();
  }
  #pragma unroll
  for (int p = 0; p < 4; p++) {
    int m = m0 + ty*4 + p;
    #pragma unroll
    for (int u = 0; u < 12; u++) {
      int nn = tx*12 + u;
      g_XP[(size_t)m*192 + nn] = acc[p][u] + b_ih[nn];
    }
  }
}

// ---------------- K4: GRU scan, one block per batch row ---------------------
__global__ void gru_kernel(const float* __restrict__ W_hh, const float* __restrict__ b_hh)
{
  __shared__ float h_s[64], gh_s[192], xp_s[192];
  int r = threadIdx.x;           // 0..191
  int b = blockIdx.x;
  float w[64];
  #pragma unroll
  for (int k = 0; k < 64; k++) w[k] = W_hh[r*64 + k];
  float bv = b_hh[r];
  if (r < 64) h_s[r] = 0.f;
  __syncthreads();

  const float* xp = g_XP + (size_t)b*TT*192;
  float* hs = g_HS + (size_t)b*TT*64;
  float xph = xp[r];             // prefetch t=0
  for (int t = 0; t < TT; t++) {
    float acc = bv;
    const float4* h4 = (const float4*)h_s;
    #pragma unroll
    for (int i = 0; i < 16; i++) {
      float4 v = h4[i];
      acc = fmaf(w[4*i+0], v.x, acc);
      acc = fmaf(w[4*i+1], v.y, acc);
      acc = fmaf(w[4*i+2], v.z, acc);
      acc = fmaf(w[4*i+3], v.w, acc);
    }
    gh_s[r] = acc; xp_s[r] = xph;
    __syncthreads();
    if (t + 1 < TT) xph = xp[(size_t)(t+1)*192 + r];   // prefetch next
    if (r < 64) {
      float rg = sigmoidf_(xp_s[r]      + gh_s[r]);
      float zg = sigmoidf_(xp_s[64+r]   + gh_s[64+r]);
      float ng = tanhf    (xp_s[128+r]  + rg*gh_s[128+r]);
      float hold = h_s[r];
      float hnew = (1.f - zg)*ng + zg*hold;
      h_s[r] = hnew;
      hs[(size_t)t*64 + r] = hnew;
    }
    __syncthreads();
  }
}

// ---------------- K6: readout, one warp per output --------------------------
__global__ void out_kernel(const float* __restrict__ la_W2, const float* __restrict__ la_b2,
                           float* __restrict__ out)
{
  int gw = (blockIdx.x*blockDim.x + threadIdx.x) >> 5;
  int lane = threadIdx.x & 31;
  if (gw >= NOUTS) return;
  int b = gw / (TT-1), i = gw % (TT-1);
  int lat = b*TT + i, tok = lat + 1;
  const float* hl = g_HL + (size_t)lat*MIDQ;
  int4 c4 = g_cls[tok];
  int c[4] = {c4.x, c4.y, c4.z, c4.w};
  float acc[4] = {0.f, 0.f, 0.f, 0.f};
  for (int k = lane; k < MIDQ; k += 32) {
    float h = hl[k];
    #pragma unroll
    for (int j = 0; j < 4; j++) if (c[j] >= 0) acc[j] += la_W2[c[j]*MIDQ+k]*h;
  }
  #pragma unroll
  for (int j = 0; j < 4; j++)
    #pragma unroll
    for (int o = 16; o > 0; o >>= 1) acc[j] += __shfl_xor_sync(0xffffffffu, acc[j], o);
  if (lane == 0) {
    float S = 0.f;
    #pragma unroll
    for (int j = 0; j < 4; j++) if (c[j] >= 0) S += sigmoidf_(acc[j] + la_b2[c[j]]);
    float sq = g_Sqd[tok];
    float y = g_disc[tok]*(S - sq)/(sq + 1e-6f);
    out[gw] = sigmoidf_(y);
  }
}

// ---------------- launcher --------------------------------------------------
extern "C" void kernel_launch(void* const* d_in, const int* in_sizes, int n_in,
                              void* d_out, int out_size)
{
  const float* E_q    = (const float*)d_in[0];
  const float* E_c    = (const float*)d_in[1];
  const float* E_it   = (const float*)d_in[2];
  const float* E_ut   = (const float*)d_in[3];
  const float* E_nh   = (const float*)d_in[4];
  const float* W_fuse = (const float*)d_in[5];
  const float* b_fuse = (const float*)d_in[6];
  const float* W_ih   = (const float*)d_in[7];
  const float* b_ih   = (const float*)d_in[8];
  const float* W_hh   = (const float*)d_in[9];
  const float* b_hh   = (const float*)d_in[10];
  const float* qd_W1  = (const float*)d_in[11];
  const float* qd_b1  = (const float*)d_in[12];
  const float* qd_W2  = (const float*)d_in[13];
  const float* qd_b2  = (const float*)d_in[14];
  const float* la_W1  = (const float*)d_in[15];
  const float* la_b1  = (const float*)d_in[16];
  const float* la_W2  = (const float*)d_in[17];
  const float* la_b2  = (const float*)d_in[18];
  const float* dc_W1  = (const float*)d_in[19];
  const float* dc_b1  = (const float*)d_in[20];
  const float* dc_W2  = (const float*)d_in[21];
  const float* dc_b2  = (const float*)d_in[22];

  // Q_table (size 2000200) sits either at slot 31 (setup order) or 23 (signature order)
  int off = (in_sizes[23] > 1000000) ? 1 : 0;
  const int* qseq  = (const int*)d_in[23+off];
  const int* cseq  = (const int*)d_in[24+off];
  const int* itseq = (const int*)d_in[25+off];
  const int* utseq = (const int*)d_in[26+off];
  const int* nhseq = (const int*)d_in[27+off];
  const int* naseq = (const int*)d_in[28+off];
  const int* q2c   = (const int*)d_in[29+off];
  const int* q2cm  = (const int*)d_in[30+off];

  float *pHQ, *pHS, *pHL;
  cudaGetSymbolAddress((void**)&pHQ, g_HQ);
  cudaGetSymbolAddress((void**)&pHS, g_HS);
  cudaGetSymbolAddress((void**)&pHL, g_HL);

  const int FEAT_SMEM = 64*193*sizeof(float);   // 49408 > 48KB default
  cudaFuncSetAttribute(features_kernel, cudaFuncAttributeMaxDynamicSharedMemorySize, FEAT_SMEM);

  hidden132_kernel<<<NTOK/128, 160>>>(qd_W1, qd_b1, E_q, qseq, pHQ);
  features_kernel<<<NTOK/64, 128, FEAT_SMEM>>>(E_q, E_c, E_it, E_ut, E_nh,
      W_fuse, b_fuse, qd_W2, qd_b2, dc_W1, dc_b1, dc_W2, dc_b2,
      qseq, cseq, itseq, utseq, nhseq, naseq, q2c, q2cm);
  xp_gemm_kernel<<<NTOK/64, 256>>>(W_ih, b_ih);
  gru_kernel<<<BB, 192>>>(W_hh, b_hh);
  hidden132_kernel<<<NTOK/128, 160>>>(la_W1, la_b1, pHS, nullptr, pHL);
  out_kernel<<<NOUTS/8, 256>>>(la_W2, la_b2, (float*)d_out);
}

// round 2
// speedup vs baseline: 3.4194x; 3.4194x over previous
#include <cuda_runtime.h>
#include <math.h>

#define BB 512
#define TT 200
#define NTOK (BB*TT)          // 102400
#define MIDQ 132
#define NOUTS (BB*(TT-1))     // 101888
#define NQ 10001

// ---------------- scratch (device globals; no allocation) ----------------
__device__ float g_TQ [NQ*192];      // per-question XP contribution (qe + ce parts)
__device__ float g_Tc [201*192];
__device__ float g_Tit[101*192];
__device__ float g_Tut[101*192];
__device__ float g_Tnh[101*192];
__device__ float g_Tna[101*192];
__device__ float g_c0[192], g_s3[192];
__device__ float g_XP[NTOK*192];
__device__ float g_HS[NTOK*64];
__device__ float g_HL[NTOK*MIDQ];
__device__ float g_qdisc[NQ], g_qSqd[NQ];
__device__ int4  g_qcls[NQ];

__device__ __forceinline__ float sigmoidf_(float x){ return 1.f/(1.f+expf(-x)); }

// ---------------- T0: small linear tables -----------------------------------
__global__ void tables_kernel(const float* __restrict__ E_c, const float* __restrict__ E_it,
                              const float* __restrict__ E_ut, const float* __restrict__ E_nh,
                              const float* __restrict__ W_ih, const float* __restrict__ b_ih,
                              const float* __restrict__ W_fuse, const float* __restrict__ b_fuse)
{
  __shared__ float e_s[64];
  __shared__ float tmp_s[64];
  int b = blockIdx.x, g = threadIdx.x;
  if (b < 201) {                       // T_c = E_c @ W2^T
    if (g < 64) e_s[g] = E_c[b*64+g];
    __syncthreads();
    float acc = 0.f;
    #pragma unroll 8
    for (int k = 0; k < 64; k++) acc = fmaf(W_ih[g*320+64+k], e_s[k], acc);
    g_Tc[b*192+g] = acc;
  } else if (b < 302) {                // T_it = E_it @ W4^T
    int u = b - 201;
    if (g < 64) e_s[g] = E_it[u*64+g];
    __syncthreads();
    float acc = 0.f;
    #pragma unroll 8
    for (int k = 0; k < 64; k++) acc = fmaf(W_ih[g*320+192+k], e_s[k], acc);
    g_Tit[u*192+g] = acc;
  } else if (b < 605) {                // T_ut / T_nh / T_na via fuse path
    int which = (b-302)/101, u = (b-302)%101;
    const float* E = (which == 0) ? E_ut : E_nh;
    int off = which*64;
    if (g < 64) e_s[g] = E[u*64+g];
    __syncthreads();
    if (g < 64) {
      float acc = 0.f;
      #pragma unroll 8
      for (int k = 0; k < 64; k++) acc = fmaf(W_fuse[g*192+off+k], e_s[k], acc);
      tmp_s[g] = acc;
    }
    __syncthreads();
    float acc = 0.f;
    #pragma unroll 8
    for (int d = 0; d < 64; d++) acc = fmaf(W_ih[g*320+256+d], tmp_s[d], acc);
    float* dst = (which == 0) ? g_Tut : (which == 1) ? g_Tnh : g_Tna;
    dst[u*192+g] = acc;
  } else {                             // c0 and s3
    float acc = b_ih[g], s = 0.f;
    #pragma unroll 8
    for (int d = 0; d < 64; d++) {
      acc = fmaf(W_ih[g*320+256+d], b_fuse[d], acc);
      s += W_ih[g*320+128+d];
    }
    g_c0[g] = acc; g_s3[g] = s;
  }
}

// ---------------- T1: g_TQ = E_q @ W1^T (10001 x 192, K=64) -----------------
__global__ void tq_gemm_kernel(const float* __restrict__ E_q, const float* __restrict__ W_ih)
{
  __shared__ float Xs[32*65];
  __shared__ float Ws[32*193];
  int tid = threadIdx.x;
  int tx = tid & 15, ty = tid >> 4;
  int m0 = blockIdx.x * 64;
  float acc[4][12];
  #pragma unroll
  for (int p = 0; p < 4; p++)
    #pragma unroll
    for (int u = 0; u < 12; u++) acc[p][u] = 0.f;

  for (int kb = 0; kb < 64; kb += 32) {
    for (int i = tid; i < 64*32; i += 256) {
      int m = i >> 5, kk = i & 31;
      int row = m0 + m;
      Xs[kk*65+m] = (row < NQ) ? E_q[row*64 + kb + kk] : 0.f;
    }
    for (int i = tid; i < 192*32; i += 256) {
      int nn = i >> 5, kk = i & 31;
      Ws[kk*193+nn] = W_ih[nn*320 + kb + kk];
    }
    __syncthreads();
    #pragma unroll
    for (int kk = 0; kk < 32; kk++) {
      float a[4], bb[12];
      #pragma unroll
      for (int p = 0; p < 4; p++) a[p] = Xs[kk*65 + ty*4 + p];
      #pragma unroll
      for (int u = 0; u < 12; u++) bb[u] = Ws[kk*193 + tx*12 + u];
      #pragma unroll
      for (int p = 0; p < 4; p++)
        #pragma unroll
        for (int u = 0; u < 12; u++) acc[p][u] = fmaf(a[p], bb[u], acc[p][u]);
    }
    __syncthreads();
  }
  #pragma unroll
  for (int p = 0; p < 4; p++) {
    int m = m0 + ty*4 + p;
    if (m < NQ) {
      #pragma unroll
      for (int u = 0; u < 12; u++) g_TQ[(size_t)m*192 + tx*12 + u] = acc[p][u];
    }
  }
}

// ---------------- P1: per-question qd/rel/disc + fold ce into TQ ------------
#define QB 8
__global__ void p1_kernel(const float* __restrict__ E_q,
                          const float* __restrict__ qd_W1, const float* __restrict__ qd_b1,
                          const float* __restrict__ qd_W2, const float* __restrict__ qd_b2,
                          const float* __restrict__ dc_W1, const float* __restrict__ dc_b1,
                          const float* __restrict__ dc_W2, const float* __restrict__ dc_b2,
                          const int* __restrict__ q2c, const int* __restrict__ q2cm)
{
  __shared__ float W1s[64*MIDQ];     // [k][t]
  __shared__ float dc1[64*32];       // [k][l]
  __shared__ float qb1s[MIDQ], dc2s[32], dcb1s[32];
  __shared__ float qe_s[64], hq_s[MIDQ];
  __shared__ float qd_s[4], w_s[4];
  __shared__ int cls_s[4], msk_s[4];
  __shared__ float dcb2s;

  int tid = threadIdx.x;
  for (int i = tid; i < MIDQ*64; i += 256) { int r = i/64, k = i%64; W1s[k*MIDQ+r] = qd_W1[i]; }
  for (int i = tid; i < 32*64;   i += 256) { int l = i/64, k = i%64; dc1[k*32+l] = dc_W1[i]; }
  if (tid < MIDQ) qb1s[tid] = qd_b1[tid];
  if (tid >= 132 && tid < 164) dc2s[tid-132] = dc_W2[tid-132];
  if (tid >= 164 && tid < 196) dcb1s[tid-164] = dc_b1[tid-164];
  if (tid == 200) dcb2s = dc_b2[0];
  __syncthreads();

  int lane = tid & 31, wid = tid >> 5;

  for (int qi = 0; qi < QB; qi++) {
    int q = blockIdx.x*QB + qi;
    if (q >= NQ) break;
    if (tid < 64) qe_s[tid] = E_q[q*64+tid];
    __syncthreads();

    if (tid < MIDQ) {                 // HQ = relu(qd_W1 @ qe + b1)
      float a0 = qb1s[tid], a1 = 0.f;
      #pragma unroll
      for (int k = 0; k < 64; k += 2) {
        a0 = fmaf(W1s[k*MIDQ+tid],     qe_s[k],   a0);
        a1 = fmaf(W1s[(k+1)*MIDQ+tid], qe_s[k+1], a1);
      }
      hq_s[tid] = fmaxf(a0 + a1, 0.f);
    } else if (wid == 5) {            // discrimination head
      float acc = dcb1s[lane];
      #pragma unroll 8
      for (int k = 0; k < 64; k++) acc = fmaf(dc1[k*32+lane], qe_s[k], acc);
      float v = dc2s[lane]*fmaxf(acc, 0.f);
      #pragma unroll
      for (int o = 16; o > 0; o >>= 1) v += __shfl_xor_sync(0xffffffffu, v, o);
      if (lane == 0) g_qdisc[q] = sigmoidf_(v + dcb2s)*10.f;
    }
    __syncthreads();

    if (wid < 4) {                    // qd at the 4 candidate classes
      int c = q2c[q*4+wid], m = q2cm[q*4+wid];
      float acc = 0.f;
      #pragma unroll
      for (int k = lane; k < MIDQ; k += 32) acc = fmaf(qd_W2[c*MIDQ+k], hq_s[k], acc);
      #pragma unroll
      for (int o = 16; o > 0; o >>= 1) acc += __shfl_xor_sync(0xffffffffu, acc, o);
      if (lane == 0) { qd_s[wid] = sigmoidf_(acc + qd_b2[c]); cls_s[wid] = c; msk_s[wid] = m; }
    }
    __syncthreads();

    if (tid == 0) {                   // rel weights + dedup + Sqd
      float rel[4], srel = 1e-6f;
      #pragma unroll
      for (int j = 0; j < 4; j++) { rel[j] = qd_s[j]*(float)msk_s[j]; srel += rel[j]; }
      #pragma unroll
      for (int j = 0; j < 4; j++) w_s[j] = rel[j]/srel;
      float S = 0.f; int cl[4];
      #pragma unroll
      for (int j = 0; j < 4; j++) {
        int c = cls_s[j]; bool fl = (msk_s[j] != 0);
        for (int j2 = 0; j2 < j; j2++) if (msk_s[j2] != 0 && cls_s[j2] == c) fl = false;
        if (fl) { S += qd_s[j]; cl[j] = c; } else cl[j] = -1;
      }
      g_qSqd[q] = S;
      g_qcls[q] = make_int4(cl[0], cl[1], cl[2], cl[3]);
    }
    __syncthreads();

    if (tid < 192) {                  // fold ce contribution into TQ
      float v = g_TQ[(size_t)q*192 + tid];
      #pragma unroll
      for (int j = 0; j < 4; j++) v = fmaf(w_s[j], g_Tc[cls_s[j]*192 + tid], v);
      g_TQ[(size_t)q*192 + tid] = v;
    }
    __syncthreads();
  }
}

// ---------------- P2: XP[n] = gather-sum of tables --------------------------
__global__ void xp_kernel(const int* __restrict__ qseq, const int* __restrict__ cseq,
                          const int* __restrict__ itseq, const int* __restrict__ utseq,
                          const int* __restrict__ nhseq, const int* __restrict__ naseq)
{
  __shared__ int qi[32], iti[32], uti[32], nhi[32], nai[32];
  __shared__ float cri[32];
  int tid = threadIdx.x;
  int n0 = blockIdx.x*32;
  int grp = tid >> 5, l = tid & 31;
  if (grp == 0) qi[l]  = qseq [n0+l];
  else if (grp == 1) cri[l] = (float)cseq[n0+l];
  else if (grp == 2) iti[l] = itseq[n0+l];
  else if (grp == 3) uti[l] = utseq[n0+l];
  else if (grp == 4) nhi[l] = nhseq[n0+l];
  else               nai[l] = naseq[n0+l];
  __syncthreads();

  int sub = tid/48, c4 = tid%48;
  float4 s3v = ((const float4*)g_s3)[c4];
  float4 c0v = ((const float4*)g_c0)[c4];
  const float4* TQ4  = (const float4*)g_TQ;
  const float4* Tit4 = (const float4*)g_Tit;
  const float4* Tut4 = (const float4*)g_Tut;
  const float4* Tnh4 = (const float4*)g_Tnh;
  const float4* Tna4 = (const float4*)g_Tna;

  for (int tl = sub; tl < 32; tl += 4) {
    int n = n0 + tl;
    float4 v  = TQ4 [(size_t)qi[tl]*48 + c4];
    float4 a  = Tit4[iti[tl]*48 + c4];
    float4 bu = Tut4[uti[tl]*48 + c4];
    float4 bh = Tnh4[nhi[tl]*48 + c4];
    float4 ba = Tna4[nai[tl]*48 + c4];
    float cr = cri[tl];
    float4 o;
    o.x = v.x + a.x + bu.x + bh.x + ba.x + cr*s3v.x + c0v.x;
    o.y = v.y + a.y + bu.y + bh.y + ba.y + cr*s3v.y + c0v.y;
    o.z = v.z + a.z + bu.z + bh.z + ba.z + cr*s3v.z + c0v.z;
    o.w = v.w + a.w + bu.w + bh.w + ba.w + cr*s3v.w + c0v.w;
    ((float4*)g_XP)[(size_t)n*48 + c4] = o;
  }
}

// ---------------- K4: GRU scan, one block per batch row ---------------------
__global__ void gru_kernel(const float* __restrict__ W_hh, const float* __restrict__ b_hh)
{
  __shared__ float h_s[64], gh_s[192], xp_s[192];
  int r = threadIdx.x;           // 0..191
  int b = blockIdx.x;
  float w[64];
  #pragma unroll
  for (int k = 0; k < 64; k++) w[k] = W_hh[r*64 + k];
  float bv = b_hh[r];
  if (r < 64) h_s[r] = 0.f;
  __syncthreads();

  const float* xp = g_XP + (size_t)b*TT*192;
  float* hs = g_HS + (size_t)b*TT*64;
  float xph = xp[r];
  for (int t = 0; t < TT; t++) {
    const float4* h4 = (const float4*)h_s;
    float a0 = 0.f, a1 = 0.f, a2 = 0.f, a3 = 0.f;
    #pragma unroll
    for (int i = 0; i < 16; i++) {
      float4 v = h4[i];
      a0 = fmaf(w[4*i+0], v.x, a0);
      a1 = fmaf(w[4*i+1], v.y, a1);
      a2 = fmaf(w[4*i+2], v.z, a2);
      a3 = fmaf(w[4*i+3], v.w, a3);
    }
    gh_s[r] = bv + ((a0+a1) + (a2+a3));
    xp_s[r] = xph;
    __syncthreads();
    int tn = (t+1 < TT) ? t+1 : t;
    xph = xp[(size_t)tn*192 + r];
    if (r < 64) {
      float rg = sigmoidf_(xp_s[r]     + gh_s[r]);
      float zg = sigmoidf_(xp_s[64+r]  + gh_s[64+r]);
      float ng = tanhf    (xp_s[128+r] + rg*gh_s[128+r]);
      float hnew = (1.f - zg)*ng + zg*h_s[r];
      h_s[r] = hnew;
      hs[(size_t)t*64 + r] = hnew;
    }
    __syncthreads();
  }
}

// ---------------- K5: HL = relu(la_W1 @ h), warp-per-token ------------------
__global__ void hl_kernel(const float* __restrict__ la_W1, const float* __restrict__ la_b1)
{
  __shared__ float Ws[64*MIDQ];     // [k][o]
  __shared__ float bs[MIDQ];
  __shared__ float tile[32*68];     // 32 tokens x 64 (stride 68 keeps float4 alignment)
  int tid = threadIdx.x;
  for (int i = tid; i < MIDQ*64; i += 256) { int o = i/64, k = i%64; Ws[k*MIDQ+o] = la_W1[i]; }
  if (tid < MIDQ) bs[tid] = la_b1[tid];
  int wid = tid >> 5, lane = tid & 31;
  int n0 = blockIdx.x * 128;

  for (int ch = 0; ch < 4; ch++) {
    __syncthreads();
    for (int i = tid; i < 32*16; i += 256) {
      int rrow = i >> 4, c = i & 15;
      float4 v = ((const float4*)(g_HS + (size_t)(n0 + ch*32 + rrow)*64))[c];
      *(float4*)&tile[rrow*68 + c*4] = v;
    }
    __syncthreads();
    for (int tt = wid; tt < 32; tt += 8) {
      int n = n0 + ch*32 + tt;
      float acc[5];
      #pragma unroll
      for (int j = 0; j < 5; j++) {
        int o = lane + 32*j;
        acc[j] = (o < MIDQ) ? bs[o] : 0.f;
      }
      #pragma unroll 8
      for (int k = 0; k < 64; k++) {
        float h = tile[tt*68 + k];
        #pragma unroll
        for (int j = 0; j < 5; j++) {
          int o = lane + 32*j;
          if (j < 4 || lane < 4) acc[j] = fmaf(Ws[k*MIDQ + o], h, acc[j]);
        }
      }
      #pragma unroll
      for (int j = 0; j < 5; j++) {
        int o = lane + 32*j;
        if (o < MIDQ) g_HL[(size_t)n*MIDQ + o] = fmaxf(acc[j], 0.f);
      }
    }
  }
}

// ---------------- K6: readout, one warp per output --------------------------
__global__ void out_kernel(const float* __restrict__ la_W2, const float* __restrict__ la_b2,
                           const int* __restrict__ qseq, float* __restrict__ out)
{
  int gw = (blockIdx.x*blockDim.x + threadIdx.x) >> 5;
  int lane = threadIdx.x & 31;
  if (gw >= NOUTS) return;
  int b = gw / (TT-1), i = gw % (TT-1);
  int lat = b*TT + i, tok = lat + 1;
  int q = qseq[tok];
  const float* hl = g_HL + (size_t)lat*MIDQ;
  int4 c4 = g_qcls[q];
  int c[4] = {c4.x, c4.y, c4.z, c4.w};
  float acc[4] = {0.f, 0.f, 0.f, 0.f};
  for (int k = lane; k < MIDQ; k += 32) {
    float h = hl[k];
    #pragma unroll
    for (int j = 0; j < 4; j++) if (c[j] >= 0) acc[j] = fmaf(la_W2[c[j]*MIDQ+k], h, acc[j]);
  }
  #pragma unroll
  for (int j = 0; j < 4; j++)
    #pragma unroll
    for (int o = 16; o > 0; o >>= 1) acc[j] += __shfl_xor_sync(0xffffffffu, acc[j], o);
  if (lane == 0) {
    float S = 0.f;
    #pragma unroll
    for (int j = 0; j < 4; j++) if (c[j] >= 0) S += sigmoidf_(acc[j] + la_b2[c[j]]);
    float sq = g_qSqd[q];
    float y = g_qdisc[q]*(S - sq)/(sq + 1e-6f);
    out[gw] = sigmoidf_(y);
  }
}

// ---------------- launcher --------------------------------------------------
extern "C" void kernel_launch(void* const* d_in, const int* in_sizes, int n_in,
                              void* d_out, int out_size)
{
  const float* E_q    = (const float*)d_in[0];
  const float* E_c    = (const float*)d_in[1];
  const float* E_it   = (const float*)d_in[2];
  const float* E_ut   = (const float*)d_in[3];
  const float* E_nh   = (const float*)d_in[4];
  const float* W_fuse = (const float*)d_in[5];
  const float* b_fuse = (const float*)d_in[6];
  const float* W_ih   = (const float*)d_in[7];
  const float* b_ih   = (const float*)d_in[8];
  const float* W_hh   = (const float*)d_in[9];
  const float* b_hh   = (const float*)d_in[10];
  const float* qd_W1  = (const float*)d_in[11];
  const float* qd_b1  = (const float*)d_in[12];
  const float* qd_W2  = (const float*)d_in[13];
  const float* qd_b2  = (const float*)d_in[14];
  const float* la_W1  = (const float*)d_in[15];
  const float* la_b1  = (const float*)d_in[16];
  const float* la_W2  = (const float*)d_in[17];
  const float* la_b2  = (const float*)d_in[18];
  const float* dc_W1  = (const float*)d_in[19];
  const float* dc_b1  = (const float*)d_in[20];
  const float* dc_W2  = (const float*)d_in[21];
  const float* dc_b2  = (const float*)d_in[22];

  // Q_table (size 2000200) sits either at slot 31 (setup order) or 23 (signature order)
  int off = (in_sizes[23] > 1000000) ? 1 : 0;
  const int* qseq  = (const int*)d_in[23+off];
  const int* cseq  = (const int*)d_in[24+off];
  const int* itseq = (const int*)d_in[25+off];
  const int* utseq = (const int*)d_in[26+off];
  const int* nhseq = (const int*)d_in[27+off];
  const int* naseq = (const int*)d_in[28+off];
  const int* q2c   = (const int*)d_in[29+off];
  const int* q2cm  = (const int*)d_in[30+off];

  tables_kernel<<<606, 192>>>(E_c, E_it, E_ut, E_nh, W_ih, b_ih, W_fuse, b_fuse);
  tq_gemm_kernel<<<(NQ+63)/64, 256>>>(E_q, W_ih);
  p1_kernel<<<(NQ+QB-1)/QB, 256>>>(E_q, qd_W1, qd_b1, qd_W2, qd_b2,
                                   dc_W1, dc_b1, dc_W2, dc_b2, q2c, q2cm);
  xp_kernel<<<NTOK/32, 192>>>(qseq, cseq, itseq, utseq, nhseq, naseq);
  gru_kernel<<<BB, 192>>>(W_hh, b_hh);
  hl_kernel<<<NTOK/128, 256>>>(la_W1, la_b1);
  out_kernel<<<(NOUTS*32 + 255)/256, 256>>>(la_W2, la_b2, qseq, (float*)d_out);
}

// round 3
// speedup vs baseline: 3.7004x; 1.0822x over previous
#include <cuda_runtime.h>
#include <math.h>

#define BB 512
#define TT 200
#define NTOK (BB*TT)          // 102400
#define MIDQ 132
#define NOUTS (BB*(TT-1))     // 101888
#define NQ 10001

// ---------------- scratch (device globals; no allocation) ----------------
__device__ float g_TQ [NQ*192];
__device__ float g_HQ [NQ*MIDQ];
__device__ float g_Tc [201*192];
__device__ float g_Tit[101*192];
__device__ float g_Tut[101*192];
__device__ float g_Tnh[101*192];
__device__ float g_Tna[101*192];
__device__ float g_c0[192], g_s3[192];
__device__ float g_XP[NTOK*192];
__device__ float g_HS[NTOK*64];
__device__ float g_qdisc[NQ], g_qSqd[NQ];
__device__ int4  g_qcls[NQ];

typedef unsigned long long ull;

__device__ __forceinline__ float fsig(float x){ return __fdividef(1.f, 1.f + __expf(-x)); }
__device__ __forceinline__ float ftanh(float x){ return fmaf(2.f, fsig(2.f*x), -1.f); }

__device__ __forceinline__ ull pack2(float lo, float hi){
  ull r; asm("mov.b64 %0, {%1,%2};" : "=l"(r) : "f"(lo), "f"(hi)); return r;
}
__device__ __forceinline__ void unpack2(ull v, float& lo, float& hi){
  asm("mov.b64 {%0,%1}, %2;" : "=f"(lo), "=f"(hi) : "l"(v));
}
__device__ __forceinline__ ull ffma2(ull a, ull b, ull c){
  ull d; asm("fma.rn.f32x2 %0, %1, %2, %3;" : "=l"(d) : "l"(a), "l"(b), "l"(c)); return d;
}

// ---------------- T0: small linear tables -----------------------------------
__global__ void tables_kernel(const float* __restrict__ E_c, const float* __restrict__ E_it,
                              const float* __restrict__ E_ut, const float* __restrict__ E_nh,
                              const float* __restrict__ W_ih, const float* __restrict__ b_ih,
                              const float* __restrict__ W_fuse, const float* __restrict__ b_fuse)
{
  __shared__ float e_s[64];
  __shared__ float tmp_s[64];
  int b = blockIdx.x, g = threadIdx.x;
  if (b < 201) {
    if (g < 64) e_s[g] = E_c[b*64+g];
    __syncthreads();
    float acc = 0.f;
    #pragma unroll 8
    for (int k = 0; k < 64; k++) acc = fmaf(W_ih[g*320+64+k], e_s[k], acc);
    g_Tc[b*192+g] = acc;
  } else if (b < 302) {
    int u = b - 201;
    if (g < 64) e_s[g] = E_it[u*64+g];
    __syncthreads();
    float acc = 0.f;
    #pragma unroll 8
    for (int k = 0; k < 64; k++) acc = fmaf(W_ih[g*320+192+k], e_s[k], acc);
    g_Tit[u*192+g] = acc;
  } else if (b < 605) {
    int which = (b-302)/101, u = (b-302)%101;
    const float* E = (which == 0) ? E_ut : E_nh;
    int off = which*64;
    if (g < 64) e_s[g] = E[u*64+g];
    __syncthreads();
    if (g < 64) {
      float acc = 0.f;
      #pragma unroll 8
      for (int k = 0; k < 64; k++) acc = fmaf(W_fuse[g*192+off+k], e_s[k], acc);
      tmp_s[g] = acc;
    }
    __syncthreads();
    float acc = 0.f;
    #pragma unroll 8
    for (int d = 0; d < 64; d++) acc = fmaf(W_ih[g*320+256+d], tmp_s[d], acc);
    float* dst = (which == 0) ? g_Tut : (which == 1) ? g_Tnh : g_Tna;
    dst[u*192+g] = acc;
  } else {
    float acc = b_ih[g], s = 0.f;
    #pragma unroll 8
    for (int d = 0; d < 64; d++) {
      acc = fmaf(W_ih[g*320+256+d], b_fuse[d], acc);
      s += W_ih[g*320+128+d];
    }
    g_c0[g] = acc; g_s3[g] = s;
  }
}

// ---------------- T1: g_TQ = E_q @ W1^T (10001 x 192, K=64) -----------------
__global__ void tq_gemm_kernel(const float* __restrict__ E_q, const float* __restrict__ W_ih)
{
  __shared__ float Xs[32*65];
  __shared__ float Ws[32*193];
  int tid = threadIdx.x;
  int tx = tid & 15, ty = tid >> 4;
  int m0 = blockIdx.x * 64;
  float acc[4][12];
  #pragma unroll
  for (int p = 0; p < 4; p++)
    #pragma unroll
    for (int u = 0; u < 12; u++) acc[p][u] = 0.f;

  for (int kb = 0; kb < 64; kb += 32) {
    for (int i = tid; i < 64*32; i += 256) {
      int m = i >> 5, kk = i & 31;
      int row = m0 + m;
      Xs[kk*65+m] = (row < NQ) ? E_q[row*64 + kb + kk] : 0.f;
    }
    for (int i = tid; i < 192*32; i += 256) {
      int nn = i >> 5, kk = i & 31;
      Ws[kk*193+nn] = W_ih[nn*320 + kb + kk];
    }
    __syncthreads();
    #pragma unroll
    for (int kk = 0; kk < 32; kk++) {
      float a[4], bb[12];
      #pragma unroll
      for (int p = 0; p < 4; p++) a[p] = Xs[kk*65 + ty*4 + p];
      #pragma unroll
      for (int u = 0; u < 12; u++) bb[u] = Ws[kk*193 + tx*12 + u];
      #pragma unroll
      for (int p = 0; p < 4; p++)
        #pragma unroll
        for (int u = 0; u < 12; u++) acc[p][u] = fmaf(a[p], bb[u], acc[p][u]);
    }
    __syncthreads();
  }
  #pragma unroll
  for (int p = 0; p < 4; p++) {
    int m = m0 + ty*4 + p;
    if (m < NQ) {
      #pragma unroll
      for (int u = 0; u < 12; u++) g_TQ[(size_t)m*192 + tx*12 + u] = acc[p][u];
    }
  }
}

// ---------------- HQ: g_HQ[q] = relu(qd_W1 @ E_q[q] + b1) -------------------
__global__ void hq_kernel(const float* __restrict__ W, const float* __restrict__ bias,
                          const float* __restrict__ rows, float* __restrict__ out)
{
    __shared__ float4 tile[128][16];
    int tid = threadIdx.x;
    float w[64]; float bv = 0.f;
    if (tid < MIDQ) {
        #pragma unroll
        for (int k = 0; k < 64; k++) w[k] = W[tid*64 + k];
        bv = bias[tid];
    }
    int tok0 = blockIdx.x * 128;
    for (int i = tid; i < 128*16; i += blockDim.x) {
        int r = i >> 4, c = i & 15;
        int row = tok0 + r; if (row >= NQ) row = NQ-1;
        tile[r][c] = reinterpret_cast<const float4*>(rows + (size_t)row*64)[c];
    }
    __syncthreads();
    if (tid < MIDQ) {
        for (int r = 0; r < 128; r++) {
            if (tok0 + r >= NQ) break;
            float acc = bv;
            #pragma unroll
            for (int c = 0; c < 16; c++) {
                float4 v = tile[r][c];
                acc = fmaf(w[4*c+0], v.x, acc);
                acc = fmaf(w[4*c+1], v.y, acc);
                acc = fmaf(w[4*c+2], v.z, acc);
                acc = fmaf(w[4*c+3], v.w, acc);
            }
            out[(size_t)(tok0+r)*MIDQ + tid] = fmaxf(acc, 0.f);
        }
    }
}

// ---------------- P1b: warp-per-question heads + TQ fold --------------------
__global__ void p1b_kernel(const float* __restrict__ E_q,
                           const float* __restrict__ qd_W2, const float* __restrict__ qd_b2,
                           const float* __restrict__ dc_W1, const float* __restrict__ dc_b1,
                           const float* __restrict__ dc_W2, const float* __restrict__ dc_b2,
                           const int* __restrict__ q2c, const int* __restrict__ q2cm)
{
  __shared__ float dc1s[64*33];          // [k][l]
  int tid = threadIdx.x;
  for (int i = tid; i < 32*64; i += 256) { int l = i >> 6, k = i & 63; dc1s[k*33+l] = dc_W1[i]; }
  __syncthreads();
  int lane = tid & 31, wid = tid >> 5;
  int q = blockIdx.x*8 + wid;
  if (q >= NQ) return;

  float h0 = g_HQ[(size_t)q*MIDQ + lane];
  float h1 = g_HQ[(size_t)q*MIDQ + lane + 32];
  float h2 = g_HQ[(size_t)q*MIDQ + lane + 64];
  float h3 = g_HQ[(size_t)q*MIDQ + lane + 96];
  float h4 = (lane < 4) ? g_HQ[(size_t)q*MIDQ + lane + 128] : 0.f;

  int cR = 0, mR = 0;
  if (lane < 4) { cR = q2c[q*4+lane]; mR = q2cm[q*4+lane]; }
  int cls[4], msk[4];
  #pragma unroll
  for (int j = 0; j < 4; j++) { cls[j] = __shfl_sync(0xffffffffu, cR, j); msk[j] = __shfl_sync(0xffffffffu, mR, j); }

  float qd[4];
  #pragma unroll
  for (int j = 0; j < 4; j++) {
    const float* wr = qd_W2 + (size_t)cls[j]*MIDQ;
    float acc = h0*wr[lane] + h1*wr[lane+32] + h2*wr[lane+64] + h3*wr[lane+96];
    if (lane < 4) acc += h4*wr[lane+128];
    #pragma unroll
    for (int o = 16; o > 0; o >>= 1) acc += __shfl_xor_sync(0xffffffffu, acc, o);
    qd[j] = fsig(acc + qd_b2[cls[j]]);
  }

  float dacc = dc_b1[lane];
  #pragma unroll 8
  for (int k = 0; k < 64; k++) dacc = fmaf(dc1s[k*33+lane], E_q[q*64+k], dacc);
  float dv = dc_W2[lane]*fmaxf(dacc, 0.f);
  #pragma unroll
  for (int o = 16; o > 0; o >>= 1) dv += __shfl_xor_sync(0xffffffffu, dv, o);

  float w[4]; float srel = 1e-6f;
  #pragma unroll
  for (int j = 0; j < 4; j++) srel += qd[j]*(float)msk[j];
  #pragma unroll
  for (int j = 0; j < 4; j++) w[j] = qd[j]*(float)msk[j]/srel;
  float S = 0.f; int cl[4];
  #pragma unroll
  for (int j = 0; j < 4; j++) {
    int c = cls[j]; bool fl = (msk[j] != 0);
    for (int j2 = 0; j2 < j; j2++) if (msk[j2] != 0 && cls[j2] == c) fl = false;
    if (fl) { S += qd[j]; cl[j] = c; } else cl[j] = -1;
  }
  if (lane == 0) {
    g_qSqd[q] = S;
    g_qcls[q] = make_int4(cl[0], cl[1], cl[2], cl[3]);
    g_qdisc[q] = fsig(dv + dc_b2[0])*10.f;
  }

  #pragma unroll
  for (int g = 0; g < 6; g++) {
    int o = g*32 + lane;
    float v = g_TQ[(size_t)q*192 + o];
    #pragma unroll
    for (int j = 0; j < 4; j++) v = fmaf(w[j], g_Tc[cls[j]*192 + o], v);
    g_TQ[(size_t)q*192 + o] = v;
  }
}

// ---------------- P2: XP[n] = gather-sum of tables --------------------------
__global__ void xp_kernel(const int* __restrict__ qseq, const int* __restrict__ cseq,
                          const int* __restrict__ itseq, const int* __restrict__ utseq,
                          const int* __restrict__ nhseq, const int* __restrict__ naseq)
{
  __shared__ int qi[32], iti[32], uti[32], nhi[32], nai[32];
  __shared__ float cri[32];
  int tid = threadIdx.x;
  int n0 = blockIdx.x*32;
  int grp = tid >> 5, l = tid & 31;
  if (grp == 0) qi[l]  = qseq [n0+l];
  else if (grp == 1) cri[l] = (float)cseq[n0+l];
  else if (grp == 2) iti[l] = itseq[n0+l];
  else if (grp == 3) uti[l] = utseq[n0+l];
  else if (grp == 4) nhi[l] = nhseq[n0+l];
  else               nai[l] = naseq[n0+l];
  __syncthreads();

  int sub = tid/48, c4 = tid%48;
  float4 s3v = ((const float4*)g_s3)[c4];
  float4 c0v = ((const float4*)g_c0)[c4];
  const float4* TQ4  = (const float4*)g_TQ;
  const float4* Tit4 = (const float4*)g_Tit;
  const float4* Tut4 = (const float4*)g_Tut;
  const float4* Tnh4 = (const float4*)g_Tnh;
  const float4* Tna4 = (const float4*)g_Tna;

  for (int tl = sub; tl < 32; tl += 4) {
    int n = n0 + tl;
    float4 v  = TQ4 [(size_t)qi[tl]*48 + c4];
    float4 a  = Tit4[iti[tl]*48 + c4];
    float4 bu = Tut4[uti[tl]*48 + c4];
    float4 bh = Tnh4[nhi[tl]*48 + c4];
    float4 ba = Tna4[nai[tl]*48 + c4];
    float cr = cri[tl];
    float4 o;
    o.x = v.x + a.x + bu.x + bh.x + ba.x + cr*s3v.x + c0v.x;
    o.y = v.y + a.y + bu.y + bh.y + ba.y + cr*s3v.y + c0v.y;
    o.z = v.z + a.z + bu.z + bh.z + ba.z + cr*s3v.z + c0v.z;
    o.w = v.w + a.w + bu.w + bh.w + ba.w + cr*s3v.w + c0v.w;
    ((float4*)g_XP)[(size_t)n*48 + c4] = o;
  }
}

// ---------------- K4: GRU scan (f32x2 matvec, fast gates) -------------------
__global__ void gru_kernel(const float* __restrict__ W_hh, const float* __restrict__ b_hh)
{
  __shared__ __align__(16) float h_s[64];
  __shared__ float gh_s[192], xp_s[192];
  int r = threadIdx.x;           // 0..191
  int b = blockIdx.x;
  ull w2[32];
  const ull* wrow = (const ull*)(W_hh) + (size_t)r*32;
  #pragma unroll
  for (int i = 0; i < 32; i++) w2[i] = wrow[i];
  float bv = b_hh[r];
  if (r < 64) h_s[r] = 0.f;
  __syncthreads();

  const float* xp = g_XP + (size_t)b*TT*192;
  float* hs = g_HS + (size_t)b*TT*64;
  float xph = xp[r];
  for (int t = 0; t < TT; t++) {
    const ulonglong2* h4 = (const ulonglong2*)h_s;
    ull a0 = 0ull, a1 = 0ull, a2 = 0ull, a3 = 0ull;
    #pragma unroll
    for (int i = 0; i < 8; i++) {
      ulonglong2 p = h4[2*i], q = h4[2*i+1];
      a0 = ffma2(w2[4*i+0], p.x, a0);
      a1 = ffma2(w2[4*i+1], p.y, a1);
      a2 = ffma2(w2[4*i+2], q.x, a2);
      a3 = ffma2(w2[4*i+3], q.y, a3);
    }
    float s0,s1,s2,s3,s4,s5,s6,s7;
    unpack2(a0,s0,s1); unpack2(a1,s2,s3); unpack2(a2,s4,s5); unpack2(a3,s6,s7);
    gh_s[r] = bv + (((s0+s1)+(s2+s3)) + ((s4+s5)+(s6+s7)));
    xp_s[r] = xph;
    __syncthreads();
    int tn = (t+1 < TT) ? t+1 : t;
    xph = xp[(size_t)tn*192 + r];
    if (r < 64) {
      float rg = fsig(xp_s[r]     + gh_s[r]);
      float zg = fsig(xp_s[64+r]  + gh_s[64+r]);
      float ng = ftanh(xp_s[128+r] + rg*gh_s[128+r]);
      float hnew = (1.f - zg)*ng + zg*h_s[r];
      h_s[r] = hnew;
      hs[(size_t)t*64 + r] = hnew;
    }
    __syncthreads();
  }
}

// ---------------- K5+K6 fused: HL + readout ---------------------------------
__global__ void fout_kernel(const float* __restrict__ la_W1, const float* __restrict__ la_b1,
                            const float* __restrict__ la_W2, const float* __restrict__ la_b2,
                            const int* __restrict__ qseq, float* __restrict__ out)
{
  __shared__ ull Wp[64*68];              // [k][j], pair j packs rows (2j, 2j+1)
  __shared__ ull bp[66];
  __shared__ __align__(16) float tile[32*68];
  int tid = threadIdx.x;
  for (int i = tid; i < MIDQ*64; i += 256) {
    int rr = i >> 6, k = i & 63;
    ((float*)&Wp[k*68 + (rr>>1)])[rr & 1] = la_W1[i];
  }
  for (int i = tid; i < 66; i += 256) bp[i] = pack2(la_b1[2*i], la_b1[2*i+1]);
  int wid = tid >> 5, lane = tid & 31;
  int n0 = blockIdx.x * 128;

  for (int ch = 0; ch < 4; ch++) {
    __syncthreads();
    for (int i = tid; i < 32*16; i += 256) {
      int rr = i >> 4, c = i & 15;
      ((float4*)&tile[rr*68])[c] = ((const float4*)(g_HS + (size_t)(n0 + ch*32 + rr)*64))[c];
    }
    __syncthreads();
    for (int tt = wid; tt < 32; tt += 8) {
      int n = n0 + ch*32 + tt;
      int it = n % TT;
      if (it == TT-1) continue;
      ull a0 = bp[lane], a1 = bp[32+lane];
      ull a2 = (lane < 2) ? bp[64+lane] : 0ull;
      const float* hrow = &tile[tt*68];
      #pragma unroll 8
      for (int k = 0; k < 64; k++) {
        float hk = hrow[k];
        ull hd = pack2(hk, hk);
        a0 = ffma2(Wp[k*68 + lane],      hd, a0);
        a1 = ffma2(Wp[k*68 + 32 + lane], hd, a1);
        if (lane < 2) a2 = ffma2(Wp[k*68 + 64 + lane], hd, a2);
      }
      float v0x,v0y,v1x,v1y,v2x,v2y;
      unpack2(a0,v0x,v0y); unpack2(a1,v1x,v1y); unpack2(a2,v2x,v2y);
      v0x = fmaxf(v0x,0.f); v0y = fmaxf(v0y,0.f);
      v1x = fmaxf(v1x,0.f); v1y = fmaxf(v1y,0.f);
      v2x = fmaxf(v2x,0.f); v2y = fmaxf(v2y,0.f);

      int q = qseq[n+1];
      int4 c4 = g_qcls[q];
      float S = 0.f;
      #pragma unroll
      for (int jj = 0; jj < 4; jj++) {
        int c = (jj==0)?c4.x:(jj==1)?c4.y:(jj==2)?c4.z:c4.w;
        if (c < 0) continue;
        const float2* row2 = (const float2*)(la_W2 + (size_t)c*MIDQ);
        float2 p0 = row2[lane], p1 = row2[32+lane];
        float acc = v0x*p0.x + v0y*p0.y + v1x*p1.x + v1y*p1.y;
        if (lane < 2) { float2 p2 = row2[64+lane]; acc += v2x*p2.x + v2y*p2.y; }
        #pragma unroll
        for (int o = 16; o > 0; o >>= 1) acc += __shfl_xor_sync(0xffffffffu, acc, o);
        if (lane == 0) S += fsig(acc + la_b2[c]);
      }
      if (lane == 0) {
        float sq = g_qSqd[q];
        float y = g_qdisc[q]*__fdividef(S - sq, sq + 1e-6f);
        int bb = n / TT;
        out[bb*(TT-1) + it] = fsig(y);
      }
    }
  }
}

// ---------------- launcher --------------------------------------------------
extern "C" void kernel_launch(void* const* d_in, const int* in_sizes, int n_in,
                              void* d_out, int out_size)
{
  const float* E_q    = (const float*)d_in[0];
  const float* E_c    = (const float*)d_in[1];
  const float* E_it   = (const float*)d_in[2];
  const float* E_ut   = (const float*)d_in[3];
  const float* E_nh   = (const float*)d_in[4];
  const float* W_fuse = (const float*)d_in[5];
  const float* b_fuse = (const float*)d_in[6];
  const float* W_ih   = (const float*)d_in[7];
  const float* b_ih   = (const float*)d_in[8];
  const float* W_hh   = (const float*)d_in[9];
  const float* b_hh   = (const float*)d_in[10];
  const float* qd_W1  = (const float*)d_in[11];
  const float* qd_b1  = (const float*)d_in[12];
  const float* qd_W2  = (const float*)d_in[13];
  const float* qd_b2  = (const float*)d_in[14];
  const float* la_W1  = (const float*)d_in[15];
  const float* la_b1  = (const float*)d_in[16];
  const float* la_W2  = (const float*)d_in[17];
  const float* la_b2  = (const float*)d_in[18];
  const float* dc_W1  = (const float*)d_in[19];
  const float* dc_b1  = (const float*)d_in[20];
  const float* dc_W2  = (const float*)d_in[21];
  const float* dc_b2  = (const float*)d_in[22];

  int off = (in_sizes[23] > 1000000) ? 1 : 0;
  const int* qseq  = (const int*)d_in[23+off];
  const int* cseq  = (const int*)d_in[24+off];
  const int* itseq = (const int*)d_in[25+off];
  const int* utseq = (const int*)d_in[26+off];
  const int* nhseq = (const int*)d_in[27+off];
  const int* naseq = (const int*)d_in[28+off];
  const int* q2c   = (const int*)d_in[29+off];
  const int* q2cm  = (const int*)d_in[30+off];

  float* pHQ; cudaGetSymbolAddress((void**)&pHQ, g_HQ);

  tables_kernel<<<606, 192>>>(E_c, E_it, E_ut, E_nh, W_ih, b_ih, W_fuse, b_fuse);
  tq_gemm_kernel<<<(NQ+63)/64, 256>>>(E_q, W_ih);
  hq_kernel<<<(NQ+127)/128, 160>>>(qd_W1, qd_b1, E_q, pHQ);
  p1b_kernel<<<(NQ+7)/8, 256>>>(E_q, qd_W2, qd_b2, dc_W1, dc_b1, dc_W2, dc_b2, q2c, q2cm);
  xp_kernel<<<NTOK/32, 192>>>(qseq, cseq, itseq, utseq, nhseq, naseq);
  gru_kernel<<<BB, 192>>>(W_hh, b_hh);
  fout_kernel<<<NTOK/128, 256>>>(la_W1, la_b1, la_W2, la_b2, qseq, (float*)d_out);
}

// round 4
// speedup vs baseline: 3.9116x; 1.0571x over previous
#include <cuda_runtime.h>
#include <math.h>

#define BB 512
#define TT 200
#define NTOK (BB*TT)          // 102400
#define MIDQ 132
#define NOUTS (BB*(TT-1))     // 101888
#define NQ 10001

// ---------------- scratch (device globals; no allocation) ----------------
__device__ float g_TQ [NQ*192];
__device__ float g_HQ [NQ*MIDQ];
__device__ float g_Tc [201*192];
__device__ float g_Tit[101*192];
__device__ float g_Tut[101*192];
__device__ float g_Tnh[101*192];
__device__ float g_Tna[101*192];
__device__ float g_c0[192], g_s3[192];
__device__ float g_XP[NTOK*192];
__device__ float g_HS[NTOK*64];
__device__ float g_qdisc[NQ], g_qSqd[NQ];
__device__ int4  g_qcls[NQ];

typedef unsigned long long ull;

__device__ __forceinline__ float fsig(float x){ return __fdividef(1.f, 1.f + __expf(-x)); }
__device__ __forceinline__ float tanha(float x){ float y; asm("tanh.approx.f32 %0,%1;" : "=f"(y) : "f"(x)); return y; }
__device__ __forceinline__ float siga(float x){ return fmaf(0.5f, tanha(0.5f*x), 0.5f); }

__device__ __forceinline__ ull pack2(float lo, float hi){
  ull r; asm("mov.b64 %0, {%1,%2};" : "=l"(r) : "f"(lo), "f"(hi)); return r;
}
__device__ __forceinline__ void unpack2(ull v, float& lo, float& hi){
  asm("mov.b64 {%0,%1}, %2;" : "=f"(lo), "=f"(hi) : "l"(v));
}
__device__ __forceinline__ ull ffma2(ull a, ull b, ull c){
  ull d; asm("fma.rn.f32x2 %0, %1, %2, %3;" : "=l"(d) : "l"(a), "l"(b), "l"(c)); return d;
}

// ---------------- T0: small linear tables -----------------------------------
__global__ void tables_kernel(const float* __restrict__ E_c, const float* __restrict__ E_it,
                              const float* __restrict__ E_ut, const float* __restrict__ E_nh,
                              const float* __restrict__ W_ih, const float* __restrict__ b_ih,
                              const float* __restrict__ W_fuse, const float* __restrict__ b_fuse)
{
  __shared__ float e_s[64];
  __shared__ float tmp_s[64];
  int b = blockIdx.x, g = threadIdx.x;
  if (b < 201) {
    if (g < 64) e_s[g] = E_c[b*64+g];
    __syncthreads();
    float acc = 0.f;
    #pragma unroll 8
    for (int k = 0; k < 64; k++) acc = fmaf(W_ih[g*320+64+k], e_s[k], acc);
    g_Tc[b*192+g] = acc;
  } else if (b < 302) {
    int u = b - 201;
    if (g < 64) e_s[g] = E_it[u*64+g];
    __syncthreads();
    float acc = 0.f;
    #pragma unroll 8
    for (int k = 0; k < 64; k++) acc = fmaf(W_ih[g*320+192+k], e_s[k], acc);
    g_Tit[u*192+g] = acc;
  } else if (b < 605) {
    int which = (b-302)/101, u = (b-302)%101;
    const float* E = (which == 0) ? E_ut : E_nh;
    int off = which*64;
    if (g < 64) e_s[g] = E[u*64+g];
    __syncthreads();
    if (g < 64) {
      float acc = 0.f;
      #pragma unroll 8
      for (int k = 0; k < 64; k++) acc = fmaf(W_fuse[g*192+off+k], e_s[k], acc);
      tmp_s[g] = acc;
    }
    __syncthreads();
    float acc = 0.f;
    #pragma unroll 8
    for (int d = 0; d < 64; d++) acc = fmaf(W_ih[g*320+256+d], tmp_s[d], acc);
    float* dst = (which == 0) ? g_Tut : (which == 1) ? g_Tnh : g_Tna;
    dst[u*192+g] = acc;
  } else {
    float acc = b_ih[g], s = 0.f;
    #pragma unroll 8
    for (int d = 0; d < 64; d++) {
      acc = fmaf(W_ih[g*320+256+d], b_fuse[d], acc);
      s += W_ih[g*320+128+d];
    }
    g_c0[g] = acc; g_s3[g] = s;
  }
}

// ---------------- T1: g_TQ = E_q @ W1^T (10001 x 192, K=64) -----------------
__global__ void tq_gemm_kernel(const float* __restrict__ E_q, const float* __restrict__ W_ih)
{
  __shared__ float Xs[32*65];
  __shared__ float Ws[32*193];
  int tid = threadIdx.x;
  int tx = tid & 15, ty = tid >> 4;
  int m0 = blockIdx.x * 64;
  float acc[4][12];
  #pragma unroll
  for (int p = 0; p < 4; p++)
    #pragma unroll
    for (int u = 0; u < 12; u++) acc[p][u] = 0.f;

  for (int kb = 0; kb < 64; kb += 32) {
    for (int i = tid; i < 64*32; i += 256) {
      int m = i >> 5, kk = i & 31;
      int row = m0 + m;
      Xs[kk*65+m] = (row < NQ) ? E_q[row*64 + kb + kk] : 0.f;
    }
    for (int i = tid; i < 192*32; i += 256) {
      int nn = i >> 5, kk = i & 31;
      Ws[kk*193+nn] = W_ih[nn*320 + kb + kk];
    }
    __syncthreads();
    #pragma unroll
    for (int kk = 0; kk < 32; kk++) {
      float a[4], bb[12];
      #pragma unroll
      for (int p = 0; p < 4; p++) a[p] = Xs[kk*65 + ty*4 + p];
      #pragma unroll
      for (int u = 0; u < 12; u++) bb[u] = Ws[kk*193 + tx*12 + u];
      #pragma unroll
      for (int p = 0; p < 4; p++)
        #pragma unroll
        for (int u = 0; u < 12; u++) acc[p][u] = fmaf(a[p], bb[u], acc[p][u]);
    }
    __syncthreads();
  }
  #pragma unroll
  for (int p = 0; p < 4; p++) {
    int m = m0 + ty*4 + p;
    if (m < NQ) {
      #pragma unroll
      for (int u = 0; u < 12; u++) g_TQ[(size_t)m*192 + tx*12 + u] = acc[p][u];
    }
  }
}

// ---------------- HQ: g_HQ[q] = relu(qd_W1 @ E_q[q] + b1), f32x2 ------------
__global__ void hq_kernel(const float* __restrict__ W, const float* __restrict__ bias,
                          const float* __restrict__ rows, float* __restrict__ out)
{
    __shared__ __align__(16) float tile[128*64];
    int tid = threadIdx.x;
    ull w2[32]; float bv = 0.f;
    if (tid < MIDQ) {
        const ull* wr = (const ull*)(W + tid*64);
        #pragma unroll
        for (int k = 0; k < 32; k++) w2[k] = wr[k];
        bv = bias[tid];
    }
    int tok0 = blockIdx.x * 128;
    for (int i = tid; i < 128*16; i += blockDim.x) {
        int r = i >> 4, c = i & 15;
        int row = tok0 + r; if (row >= NQ) row = NQ-1;
        ((float4*)tile)[r*16 + c] = ((const float4*)(rows + (size_t)row*64))[c];
    }
    __syncthreads();
    if (tid < MIDQ) {
        for (int r = 0; r < 128; r += 2) {
            if (tok0 + r >= NQ) break;
            const ulonglong2* ha = (const ulonglong2*)(tile + r*64);
            const ulonglong2* hb = (const ulonglong2*)(tile + (r+1)*64);
            ull a0=0ull,a1=0ull,b0=0ull,b1=0ull;
            #pragma unroll
            for (int i2 = 0; i2 < 16; i2++) {
                ulonglong2 pa = ha[i2], pb = hb[i2];
                a0 = ffma2(w2[2*i2],   pa.x, a0);
                a1 = ffma2(w2[2*i2+1], pa.y, a1);
                b0 = ffma2(w2[2*i2],   pb.x, b0);
                b1 = ffma2(w2[2*i2+1], pb.y, b1);
            }
            float p0,p1,p2,p3,q0,q1,q2,q3;
            unpack2(a0,p0,p1); unpack2(a1,p2,p3);
            unpack2(b0,q0,q1); unpack2(b1,q2,q3);
            out[(size_t)(tok0+r)*MIDQ + tid] = fmaxf(bv + (p0+p1)+(p2+p3), 0.f);
            if (tok0+r+1 < NQ)
                out[(size_t)(tok0+r+1)*MIDQ + tid] = fmaxf(bv + (q0+q1)+(q2+q3), 0.f);
        }
    }
}

// ---------------- P1b: warp-per-question heads + TQ fold --------------------
__global__ void p1b_kernel(const float* __restrict__ E_q,
                           const float* __restrict__ qd_W2, const float* __restrict__ qd_b2,
                           const float* __restrict__ dc_W1, const float* __restrict__ dc_b1,
                           const float* __restrict__ dc_W2, const float* __restrict__ dc_b2,
                           const int* __restrict__ q2c, const int* __restrict__ q2cm)
{
  __shared__ float dc1s[64*33];
  int tid = threadIdx.x;
  for (int i = tid; i < 32*64; i += 256) { int l = i >> 6, k = i & 63; dc1s[k*33+l] = dc_W1[i]; }
  __syncthreads();
  int lane = tid & 31, wid = tid >> 5;
  int q = blockIdx.x*8 + wid;
  if (q >= NQ) return;

  float h0 = g_HQ[(size_t)q*MIDQ + lane];
  float h1 = g_HQ[(size_t)q*MIDQ + lane + 32];
  float h2 = g_HQ[(size_t)q*MIDQ + lane + 64];
  float h3 = g_HQ[(size_t)q*MIDQ + lane + 96];
  float h4 = (lane < 4) ? g_HQ[(size_t)q*MIDQ + lane + 128] : 0.f;

  int cR = 0, mR = 0;
  if (lane < 4) { cR = q2c[q*4+lane]; mR = q2cm[q*4+lane]; }
  int cls[4], msk[4];
  #pragma unroll
  for (int j = 0; j < 4; j++) { cls[j] = __shfl_sync(0xffffffffu, cR, j); msk[j] = __shfl_sync(0xffffffffu, mR, j); }

  float qd[4];
  #pragma unroll
  for (int j = 0; j < 4; j++) {
    const float* wr = qd_W2 + (size_t)cls[j]*MIDQ;
    float acc = h0*wr[lane] + h1*wr[lane+32] + h2*wr[lane+64] + h3*wr[lane+96];
    if (lane < 4) acc += h4*wr[lane+128];
    #pragma unroll
    for (int o = 16; o > 0; o >>= 1) acc += __shfl_xor_sync(0xffffffffu, acc, o);
    qd[j] = fsig(acc + qd_b2[cls[j]]);
  }

  float dacc = dc_b1[lane];
  #pragma unroll 8
  for (int k = 0; k < 64; k++) dacc = fmaf(dc1s[k*33+lane], E_q[q*64+k], dacc);
  float dv = dc_W2[lane]*fmaxf(dacc, 0.f);
  #pragma unroll
  for (int o = 16; o > 0; o >>= 1) dv += __shfl_xor_sync(0xffffffffu, dv, o);

  float w[4]; float srel = 1e-6f;
  #pragma unroll
  for (int j = 0; j < 4; j++) srel += qd[j]*(float)msk[j];
  #pragma unroll
  for (int j = 0; j < 4; j++) w[j] = qd[j]*(float)msk[j]/srel;
  float S = 0.f; int cl[4];
  #pragma unroll
  for (int j = 0; j < 4; j++) {
    int c = cls[j]; bool fl = (msk[j] != 0);
    for (int j2 = 0; j2 < j; j2++) if (msk[j2] != 0 && cls[j2] == c) fl = false;
    if (fl) { S += qd[j]; cl[j] = c; } else cl[j] = -1;
  }
  if (lane == 0) {
    g_qSqd[q] = S;
    g_qcls[q] = make_int4(cl[0], cl[1], cl[2], cl[3]);
    g_qdisc[q] = fsig(dv + dc_b2[0])*10.f;
  }

  #pragma unroll
  for (int g = 0; g < 6; g++) {
    int o = g*32 + lane;
    float v = g_TQ[(size_t)q*192 + o];
    #pragma unroll
    for (int j = 0; j < 4; j++) v = fmaf(w[j], g_Tc[cls[j]*192 + o], v);
    g_TQ[(size_t)q*192 + o] = v;
  }
}

// ---------------- P2: XP[n] = gather-sum of tables --------------------------
__global__ void xp_kernel(const int* __restrict__ qseq, const int* __restrict__ cseq,
                          const int* __restrict__ itseq, const int* __restrict__ utseq,
                          const int* __restrict__ nhseq, const int* __restrict__ naseq)
{
  __shared__ int qi[32], iti[32], uti[32], nhi[32], nai[32];
  __shared__ float cri[32];
  int tid = threadIdx.x;
  int n0 = blockIdx.x*32;
  int grp = tid >> 5, l = tid & 31;
  if (grp == 0) qi[l]  = qseq [n0+l];
  else if (grp == 1) cri[l] = (float)cseq[n0+l];
  else if (grp == 2) iti[l] = itseq[n0+l];
  else if (grp == 3) uti[l] = utseq[n0+l];
  else if (grp == 4) nhi[l] = nhseq[n0+l];
  else               nai[l] = naseq[n0+l];
  __syncthreads();

  int sub = tid/48, c4 = tid%48;
  float4 s3v = ((const float4*)g_s3)[c4];
  float4 c0v = ((const float4*)g_c0)[c4];
  const float4* TQ4  = (const float4*)g_TQ;
  const float4* Tit4 = (const float4*)g_Tit;
  const float4* Tut4 = (const float4*)g_Tut;
  const float4* Tnh4 = (const float4*)g_Tnh;
  const float4* Tna4 = (const float4*)g_Tna;

  for (int tl = sub; tl < 32; tl += 4) {
    int n = n0 + tl;
    float4 v  = TQ4 [(size_t)qi[tl]*48 + c4];
    float4 a  = Tit4[iti[tl]*48 + c4];
    float4 bu = Tut4[uti[tl]*48 + c4];
    float4 bh = Tnh4[nhi[tl]*48 + c4];
    float4 ba = Tna4[nai[tl]*48 + c4];
    float cr = cri[tl];
    float4 o;
    o.x = v.x + a.x + bu.x + bh.x + ba.x + cr*s3v.x + c0v.x;
    o.y = v.y + a.y + bu.y + bh.y + ba.y + cr*s3v.y + c0v.y;
    o.z = v.z + a.z + bu.z + bh.z + ba.z + cr*s3v.z + c0v.z;
    o.w = v.w + a.w + bu.w + bh.w + ba.w + cr*s3v.w + c0v.w;
    ((float4*)g_XP)[(size_t)n*48 + c4] = o;
  }
}

// ---------------- K4: GRU scan (split named barriers, 1 wave) ---------------
__global__ void __launch_bounds__(192, 4) gru_kernel(const float* __restrict__ W_hh,
                                                     const float* __restrict__ b_hh)
{
  __shared__ __align__(16) float h_s[64];
  __shared__ float gh_s[192];
  int r = threadIdx.x;           // 0..191
  int b = blockIdx.x;
  ull w2[32];
  const ull* wrow = (const ull*)(W_hh) + (size_t)r*32;
  #pragma unroll
  for (int i = 0; i < 32; i++) w2[i] = wrow[i];
  float bv = b_hh[r];
  if (r < 64) h_s[r] = 0.f;
  __syncthreads();

  const float* xp = g_XP + (size_t)b*TT*192;
  float* hs = g_HS + (size_t)b*TT*64;
  bool upd = (r < 64);
  float x0 = 0.f, x1 = 0.f, x2 = 0.f;
  if (upd) { x0 = xp[r]; x1 = xp[64+r]; x2 = xp[128+r]; }

  for (int t = 0; t < TT; t++) {
    ull a0=0ull,a1=0ull,a2=0ull,a3=0ull;
    const ulonglong2* h4 = (const ulonglong2*)h_s;
    #pragma unroll
    for (int i = 0; i < 8; i++) {
      ulonglong2 p = h4[2*i], q = h4[2*i+1];
      a0 = ffma2(w2[4*i+0], p.x, a0);
      a1 = ffma2(w2[4*i+1], p.y, a1);
      a2 = ffma2(w2[4*i+2], q.x, a2);
      a3 = ffma2(w2[4*i+3], q.y, a3);
    }
    float s0,s1,s2,s3,s4,s5,s6,s7;
    unpack2(a0,s0,s1); unpack2(a1,s2,s3); unpack2(a2,s4,s5); unpack2(a3,s6,s7);
    gh_s[r] = bv + (((s0+s1)+(s2+s3)) + ((s4+s5)+(s6+s7)));
    if (upd) {
      // prefetch next xp while waiting for gh from other warps
      float nx0 = x0, nx1 = x1, nx2 = x2;
      if (t+1 < TT) {
        const float* xn = xp + (size_t)(t+1)*192;
        nx0 = xn[r]; nx1 = xn[64+r]; nx2 = xn[128+r];
      }
      asm volatile("bar.sync 0, 192;" ::: "memory");
      float rg = siga(x0 + gh_s[r]);
      float zg = siga(x1 + gh_s[64+r]);
      float ng = tanha(fmaf(rg, gh_s[128+r], x2));
      float hnew = fmaf(zg, h_s[r] - ng, ng);   // n + z*(h-n)
      h_s[r] = hnew;
      hs[(size_t)t*64 + r] = hnew;
      x0 = nx0; x1 = nx1; x2 = nx2;
      asm volatile("bar.arrive 2, 192;" ::: "memory");
      asm volatile("bar.sync 1, 64;" ::: "memory");
    } else {
      asm volatile("bar.arrive 0, 192;" ::: "memory");
      asm volatile("bar.sync 2, 192;" ::: "memory");
    }
  }
}

// ---------------- K5+K6 fused: HL + readout (token-pair f32x2) --------------
__global__ void __launch_bounds__(256, 2) fout_kernel(
                            const float* __restrict__ la_W1, const float* __restrict__ la_b1,
                            const float* __restrict__ la_W2, const float* __restrict__ la_b2,
                            const int* __restrict__ qseq, float* __restrict__ out)
{
  extern __shared__ char sm_[];
  float* Ws = (float*)sm_;                       // [k][row] 64*132 floats
  float* bs = Ws + 64*132;                       // 132 floats
  ull*   tp = (ull*)(sm_ + ((64*132 + 132)*4));  // [pair][k] 64*66 ulls (34320 % 8 == 0)

  int tid = threadIdx.x, lane = tid & 31, wid = tid >> 5;
  int n0 = blockIdx.x * 128;

  for (int i = tid; i < 132*64; i += 256) {
    int row = i >> 6, k = i & 63;
    Ws[k*132 + row] = la_W1[i];
  }
  if (tid < 132) bs[tid] = la_b1[tid];
  for (int i = tid; i < 128*16; i += 256) {
    int tok = i >> 4, c = i & 15;
    float4 v = ((const float4*)(g_HS + (size_t)(n0+tok)*64))[c];
    int p = tok >> 1, e = tok & 1;
    ((float*)&tp[p*66 + 4*c + 0])[e] = v.x;
    ((float*)&tp[p*66 + 4*c + 1])[e] = v.y;
    ((float*)&tp[p*66 + 4*c + 2])[e] = v.z;
    ((float*)&tp[p*66 + 4*c + 3])[e] = v.w;
  }
  __syncthreads();

  // biases
  float b0 = bs[lane], b1v = bs[32+lane], b2v = bs[64+lane], b3v = bs[96+lane];
  float b4v = (lane < 4) ? bs[128+lane] : 0.f;
  ull acc[8][5];
  {
    ull p0=pack2(b0,b0), p1=pack2(b1v,b1v), p2=pack2(b2v,b2v), p3=pack2(b3v,b3v), p4=pack2(b4v,b4v);
    #pragma unroll
    for (int p = 0; p < 8; p++) { acc[p][0]=p0; acc[p][1]=p1; acc[p][2]=p2; acc[p][3]=p3; acc[p][4]=p4; }
  }
  int pbase = wid*8;
  #pragma unroll 2
  for (int k = 0; k < 64; k++) {
    float w0 = Ws[k*132 + lane];
    float w1 = Ws[k*132 + 32 + lane];
    float w2v = Ws[k*132 + 64 + lane];
    float w3 = Ws[k*132 + 96 + lane];
    float w4 = (lane < 4) ? Ws[k*132 + 128 + lane] : 0.f;
    ull d0=pack2(w0,w0), d1=pack2(w1,w1), d2=pack2(w2v,w2v), d3=pack2(w3,w3), d4=pack2(w4,w4);
    #pragma unroll
    for (int p = 0; p < 8; p++) {
      ull hd = tp[(pbase+p)*66 + k];
      acc[p][0] = ffma2(d0, hd, acc[p][0]);
      acc[p][1] = ffma2(d1, hd, acc[p][1]);
      acc[p][2] = ffma2(d2, hd, acc[p][2]);
      acc[p][3] = ffma2(d3, hd, acc[p][3]);
      acc[p][4] = ffma2(d4, hd, acc[p][4]);
    }
  }

  #pragma unroll
  for (int p = 0; p < 8; p++) {
    float va[5], vb[5];
    #pragma unroll
    for (int c = 0; c < 5; c++) {
      unpack2(acc[p][c], va[c], vb[c]);
      va[c] = fmaxf(va[c], 0.f);
      vb[c] = fmaxf(vb[c], 0.f);
    }
    #pragma unroll
    for (int e = 0; e < 2; e++) {
      int n = n0 + (pbase + p)*2 + e;
      int bb = n / TT, it = n - bb*TT;
      if (it == TT-1) continue;
      float v0 = e ? vb[0] : va[0];
      float v1 = e ? vb[1] : va[1];
      float v2 = e ? vb[2] : va[2];
      float v3 = e ? vb[3] : va[3];
      float v4 = e ? vb[4] : va[4];

      int q = qseq[n+1];
      int4 c4 = g_qcls[q];
      int carr[4] = {c4.x, c4.y, c4.z, c4.w};
      float S = 0.f;
      #pragma unroll
      for (int jj = 0; jj < 4; jj++) {
        int c = carr[jj];
        if (c < 0) continue;
        const float* w2r = la_W2 + (size_t)c*MIDQ;
        float a = v0*w2r[lane] + v1*w2r[32+lane] + v2*w2r[64+lane] + v3*w2r[96+lane];
        if (lane < 4) a += v4*w2r[128+lane];
        #pragma unroll
        for (int o = 16; o > 0; o >>= 1) a += __shfl_xor_sync(0xffffffffu, a, o);
        if (lane == 0) S += fsig(a + la_b2[c]);
      }
      if (lane == 0) {
        float sq = g_qSqd[q];
        float y = g_qdisc[q]*__fdividef(S - sq, sq + 1e-6f);
        out[bb*(TT-1) + it] = fsig(y);
      }
    }
  }
}

// ---------------- launcher --------------------------------------------------
extern "C" void kernel_launch(void* const* d_in, const int* in_sizes, int n_in,
                              void* d_out, int out_size)
{
  const float* E_q    = (const float*)d_in[0];
  const float* E_c    = (const float*)d_in[1];
  const float* E_it   = (const float*)d_in[2];
  const float* E_ut   = (const float*)d_in[3];
  const float* E_nh   = (const float*)d_in[4];
  const float* W_fuse = (const float*)d_in[5];
  const float* b_fuse = (const float*)d_in[6];
  const float* W_ih   = (const float*)d_in[7];
  const float* b_ih   = (const float*)d_in[8];
  const float* W_hh   = (const float*)d_in[9];
  const float* b_hh   = (const float*)d_in[10];
  const float* qd_W1  = (const float*)d_in[11];
  const float* qd_b1  = (const float*)d_in[12];
  const float* qd_W2  = (const float*)d_in[13];
  const float* qd_b2  = (const float*)d_in[14];
  const float* la_W1  = (const float*)d_in[15];
  const float* la_b1  = (const float*)d_in[16];
  const float* la_W2  = (const float*)d_in[17];
  const float* la_b2  = (const float*)d_in[18];
  const float* dc_W1  = (const float*)d_in[19];
  const float* dc_b1  = (const float*)d_in[20];
  const float* dc_W2  = (const float*)d_in[21];
  const float* dc_b2  = (const float*)d_in[22];

  int off = (in_sizes[23] > 1000000) ? 1 : 0;
  const int* qseq  = (const int*)d_in[23+off];
  const int* cseq  = (const int*)d_in[24+off];
  const int* itseq = (const int*)d_in[25+off];
  const int* utseq = (const int*)d_in[26+off];
  const int* nhseq = (const int*)d_in[27+off];
  const int* naseq = (const int*)d_in[28+off];
  const int* q2c   = (const int*)d_in[29+off];
  const int* q2cm  = (const int*)d_in[30+off];

  float* pHQ; cudaGetSymbolAddress((void**)&pHQ, g_HQ);

  const int FOUT_SMEM = (64*132 + 132)*4 + 64*66*8;   // 68112 bytes
  cudaFuncSetAttribute(fout_kernel, cudaFuncAttributeMaxDynamicSharedMemorySize, FOUT_SMEM);

  tables_kernel<<<606, 192>>>(E_c, E_it, E_ut, E_nh, W_ih, b_ih, W_fuse, b_fuse);
  tq_gemm_kernel<<<(NQ+63)/64, 256>>>(E_q, W_ih);
  hq_kernel<<<(NQ+127)/128, 160>>>(qd_W1, qd_b1, E_q, pHQ);
  p1b_kernel<<<(NQ+7)/8, 256>>>(E_q, qd_W2, qd_b2, dc_W1, dc_b1, dc_W2, dc_b2, q2c, q2cm);
  xp_kernel<<<NTOK/32, 192>>>(qseq, cseq, itseq, utseq, nhseq, naseq);
  gru_kernel<<<BB, 192>>>(W_hh, b_hh);
  fout_kernel<<<NTOK/128, 256, FOUT_SMEM>>>(la_W1, la_b1, la_W2, la_b2, qseq, (float*)d_out);
}

// round 5
// speedup vs baseline: 4.6774x; 1.1958x over previous
#include <cuda_runtime.h>
#include <math.h>

#define BB 512
#define TT 200
#define NTOK (BB*TT)          // 102400
#define MIDQ 132
#define NOUTS (BB*(TT-1))     // 101888
#define NQ 10001

// ---------------- scratch (device globals; no allocation) ----------------
__device__ float g_TQ [NQ*192];
__device__ float g_HQ [NQ*MIDQ];
__device__ float g_Tc [201*192];
__device__ float g_Tit[101*192];
__device__ float g_Tut[101*192];
__device__ float g_Tnh[101*192];
__device__ float g_Tna[101*192];
__device__ float g_c0[192], g_s3[192];
__device__ float g_XP[NTOK*192];
__device__ float g_HS[NTOK*64];
__device__ float g_qdisc[NQ], g_qSqd[NQ];
__device__ int4  g_qcls[NQ];

typedef unsigned long long ull;

__device__ __forceinline__ float fsig(float x){ return __fdividef(1.f, 1.f + __expf(-x)); }
__device__ __forceinline__ float tanha(float x){ float y; asm("tanh.approx.f32 %0,%1;" : "=f"(y) : "f"(x)); return y; }
__device__ __forceinline__ float siga(float x){ return fmaf(0.5f, tanha(0.5f*x), 0.5f); }

__device__ __forceinline__ ull pack2(float lo, float hi){
  ull r; asm("mov.b64 %0, {%1,%2};" : "=l"(r) : "f"(lo), "f"(hi)); return r;
}
__device__ __forceinline__ void unpack2(ull v, float& lo, float& hi){
  asm("mov.b64 {%0,%1}, %2;" : "=f"(lo), "=f"(hi) : "l"(v));
}
__device__ __forceinline__ ull ffma2(ull a, ull b, ull c){
  ull d; asm("fma.rn.f32x2 %0, %1, %2, %3;" : "=l"(d) : "l"(a), "l"(b), "l"(c)); return d;
}

// ================= P0: fused tables + tq_gemm + hq ==========================
// blocks [0,606): tables; [606,763): TQ gemm; [763,842): HQ
__global__ void p0_kernel(const float* __restrict__ E_q, const float* __restrict__ E_c,
                          const float* __restrict__ E_it, const float* __restrict__ E_ut,
                          const float* __restrict__ E_nh,
                          const float* __restrict__ W_ih, const float* __restrict__ b_ih,
                          const float* __restrict__ W_fuse, const float* __restrict__ b_fuse,
                          const float* __restrict__ qd_W1, const float* __restrict__ qd_b1)
{
  extern __shared__ __align__(16) char ps[];
  int tid = threadIdx.x;
  int blk = blockIdx.x;

  if (blk < 606) {
    // ---------------- tables ----------------
    float* e_s  = (float*)ps;
    float* tmp_s = e_s + 64;
    int b = blk, g = tid;
    if (b < 201) {
      if (g < 64) e_s[g] = E_c[b*64+g];
      __syncthreads();
      if (g < 192) {
        float acc = 0.f;
        #pragma unroll 8
        for (int k = 0; k < 64; k++) acc = fmaf(W_ih[g*320+64+k], e_s[k], acc);
        g_Tc[b*192+g] = acc;
      }
    } else if (b < 302) {
      int u = b - 201;
      if (g < 64) e_s[g] = E_it[u*64+g];
      __syncthreads();
      if (g < 192) {
        float acc = 0.f;
        #pragma unroll 8
        for (int k = 0; k < 64; k++) acc = fmaf(W_ih[g*320+192+k], e_s[k], acc);
        g_Tit[u*192+g] = acc;
      }
    } else if (b < 605) {
      int which = (b-302)/101, u = (b-302)%101;
      const float* E = (which == 0) ? E_ut : E_nh;
      int off = which*64;
      if (g < 64) e_s[g] = E[u*64+g];
      __syncthreads();
      if (g < 64) {
        float acc = 0.f;
        #pragma unroll 8
        for (int k = 0; k < 64; k++) acc = fmaf(W_fuse[g*192+off+k], e_s[k], acc);
        tmp_s[g] = acc;
      }
      __syncthreads();
      if (g < 192) {
        float acc = 0.f;
        #pragma unroll 8
        for (int d = 0; d < 64; d++) acc = fmaf(W_ih[g*320+256+d], tmp_s[d], acc);
        float* dst = (which == 0) ? g_Tut : (which == 1) ? g_Tnh : g_Tna;
        dst[u*192+g] = acc;
      }
    } else {
      if (g < 192) {
        float acc = b_ih[g], s = 0.f;
        #pragma unroll 8
        for (int d = 0; d < 64; d++) {
          acc = fmaf(W_ih[g*320+256+d], b_fuse[d], acc);
          s += W_ih[g*320+128+d];
        }
        g_c0[g] = acc; g_s3[g] = s;
      }
    }
  } else if (blk < 763) {
    // ---------------- TQ gemm: g_TQ = E_q @ W1^T ----------------
    float* Xs  = (float*)ps;        // 32*65
    float* Wsm = Xs + 32*65;        // 32*193
    int tx = tid & 15, ty = tid >> 4;
    int m0 = (blk - 606) * 64;
    float acc[4][12];
    #pragma unroll
    for (int p = 0; p < 4; p++)
      #pragma unroll
      for (int u = 0; u < 12; u++) acc[p][u] = 0.f;

    for (int kb = 0; kb < 64; kb += 32) {
      for (int i = tid; i < 64*32; i += 256) {
        int m = i >> 5, kk = i & 31;
        int row = m0 + m;
        Xs[kk*65+m] = (row < NQ) ? E_q[row*64 + kb + kk] : 0.f;
      }
      for (int i = tid; i < 192*32; i += 256) {
        int nn = i >> 5, kk = i & 31;
        Wsm[kk*193+nn] = W_ih[nn*320 + kb + kk];
      }
      __syncthreads();
      #pragma unroll
      for (int kk = 0; kk < 32; kk++) {
        float a[4], bb[12];
        #pragma unroll
        for (int p = 0; p < 4; p++) a[p] = Xs[kk*65 + ty*4 + p];
        #pragma unroll
        for (int u = 0; u < 12; u++) bb[u] = Wsm[kk*193 + tx*12 + u];
        #pragma unroll
        for (int p = 0; p < 4; p++)
          #pragma unroll
          for (int u = 0; u < 12; u++) acc[p][u] = fmaf(a[p], bb[u], acc[p][u]);
      }
      __syncthreads();
    }
    #pragma unroll
    for (int p = 0; p < 4; p++) {
      int m = m0 + ty*4 + p;
      if (m < NQ) {
        #pragma unroll
        for (int u = 0; u < 12; u++) g_TQ[(size_t)m*192 + tx*12 + u] = acc[p][u];
      }
    }
  } else {
    // ---------------- HQ: relu(qd_W1 @ E_q + b1) ----------------
    float* tile = (float*)ps;       // 128*64
    ull w2[32]; float bv = 0.f;
    if (tid < MIDQ) {
      const ull* wr = (const ull*)(qd_W1 + tid*64);
      #pragma unroll
      for (int k = 0; k < 32; k++) w2[k] = wr[k];
      bv = qd_b1[tid];
    }
    int tok0 = (blk - 763) * 128;
    for (int i = tid; i < 128*16; i += 256) {
      int r = i >> 4, c = i & 15;
      int row = tok0 + r; if (row >= NQ) row = NQ-1;
      ((float4*)tile)[r*16 + c] = ((const float4*)(E_q + (size_t)row*64))[c];
    }
    __syncthreads();
    if (tid < MIDQ) {
      for (int r = 0; r < 128; r += 2) {
        if (tok0 + r >= NQ) break;
        const ulonglong2* ha = (const ulonglong2*)(tile + r*64);
        const ulonglong2* hb = (const ulonglong2*)(tile + (r+1)*64);
        ull a0=0ull,a1=0ull,b0=0ull,b1=0ull;
        #pragma unroll
        for (int i2 = 0; i2 < 16; i2++) {
          ulonglong2 pa = ha[i2], pb = hb[i2];
          a0 = ffma2(w2[2*i2],   pa.x, a0);
          a1 = ffma2(w2[2*i2+1], pa.y, a1);
          b0 = ffma2(w2[2*i2],   pb.x, b0);
          b1 = ffma2(w2[2*i2+1], pb.y, b1);
        }
        float p0,p1,p2,p3,q0,q1,q2,q3;
        unpack2(a0,p0,p1); unpack2(a1,p2,p3);
        unpack2(b0,q0,q1); unpack2(b1,q2,q3);
        g_HQ[(size_t)(tok0+r)*MIDQ + tid] = fmaxf(bv + (p0+p1)+(p2+p3), 0.f);
        if (tok0+r+1 < NQ)
          g_HQ[(size_t)(tok0+r+1)*MIDQ + tid] = fmaxf(bv + (q0+q1)+(q2+q3), 0.f);
      }
    }
  }
}

// ---------------- P1b: warp-per-question heads + TQ fold --------------------
__global__ void p1b_kernel(const float* __restrict__ E_q,
                           const float* __restrict__ qd_W2, const float* __restrict__ qd_b2,
                           const float* __restrict__ dc_W1, const float* __restrict__ dc_b1,
                           const float* __restrict__ dc_W2, const float* __restrict__ dc_b2,
                           const int* __restrict__ q2c, const int* __restrict__ q2cm)
{
  __shared__ float dc1s[64*33];
  int tid = threadIdx.x;
  for (int i = tid; i < 32*64; i += 256) { int l = i >> 6, k = i & 63; dc1s[k*33+l] = dc_W1[i]; }
  __syncthreads();
  int lane = tid & 31, wid = tid >> 5;
  int q = blockIdx.x*8 + wid;
  if (q >= NQ) return;

  float h0 = g_HQ[(size_t)q*MIDQ + lane];
  float h1 = g_HQ[(size_t)q*MIDQ + lane + 32];
  float h2 = g_HQ[(size_t)q*MIDQ + lane + 64];
  float h3 = g_HQ[(size_t)q*MIDQ + lane + 96];
  float h4 = (lane < 4) ? g_HQ[(size_t)q*MIDQ + lane + 128] : 0.f;

  int cR = 0, mR = 0;
  if (lane < 4) { cR = q2c[q*4+lane]; mR = q2cm[q*4+lane]; }
  int cls[4], msk[4];
  #pragma unroll
  for (int j = 0; j < 4; j++) { cls[j] = __shfl_sync(0xffffffffu, cR, j); msk[j] = __shfl_sync(0xffffffffu, mR, j); }

  float qd[4];
  #pragma unroll
  for (int j = 0; j < 4; j++) {
    const float* wr = qd_W2 + (size_t)cls[j]*MIDQ;
    float acc = h0*wr[lane] + h1*wr[lane+32] + h2*wr[lane+64] + h3*wr[lane+96];
    if (lane < 4) acc += h4*wr[lane+128];
    #pragma unroll
    for (int o = 16; o > 0; o >>= 1) acc += __shfl_xor_sync(0xffffffffu, acc, o);
    qd[j] = fsig(acc + qd_b2[cls[j]]);
  }

  float dacc = dc_b1[lane];
  #pragma unroll 8
  for (int k = 0; k < 64; k++) dacc = fmaf(dc1s[k*33+lane], E_q[q*64+k], dacc);
  float dv = dc_W2[lane]*fmaxf(dacc, 0.f);
  #pragma unroll
  for (int o = 16; o > 0; o >>= 1) dv += __shfl_xor_sync(0xffffffffu, dv, o);

  float w[4]; float srel = 1e-6f;
  #pragma unroll
  for (int j = 0; j < 4; j++) srel += qd[j]*(float)msk[j];
  #pragma unroll
  for (int j = 0; j < 4; j++) w[j] = qd[j]*(float)msk[j]/srel;
  float S = 0.f; int cl[4];
  #pragma unroll
  for (int j = 0; j < 4; j++) {
    int c = cls[j]; bool fl = (msk[j] != 0);
    for (int j2 = 0; j2 < j; j2++) if (msk[j2] != 0 && cls[j2] == c) fl = false;
    if (fl) { S += qd[j]; cl[j] = c; } else cl[j] = -1;
  }
  if (lane == 0) {
    g_qSqd[q] = S;
    g_qcls[q] = make_int4(cl[0], cl[1], cl[2], cl[3]);
    g_qdisc[q] = fsig(dv + dc_b2[0])*10.f;
  }

  #pragma unroll
  for (int g = 0; g < 6; g++) {
    int o = g*32 + lane;
    float v = g_TQ[(size_t)q*192 + o];
    #pragma unroll
    for (int j = 0; j < 4; j++) v = fmaf(w[j], g_Tc[cls[j]*192 + o], v);
    g_TQ[(size_t)q*192 + o] = v;
  }
}

// ---------------- P2: XP[n] = gather-sum of tables --------------------------
__global__ void xp_kernel(const int* __restrict__ qseq, const int* __restrict__ cseq,
                          const int* __restrict__ itseq, const int* __restrict__ utseq,
                          const int* __restrict__ nhseq, const int* __restrict__ naseq)
{
  __shared__ int qi[32], iti[32], uti[32], nhi[32], nai[32];
  __shared__ float cri[32];
  int tid = threadIdx.x;
  int n0 = blockIdx.x*32;
  int grp = tid >> 5, l = tid & 31;
  if (grp == 0) qi[l]  = qseq [n0+l];
  else if (grp == 1) cri[l] = (float)cseq[n0+l];
  else if (grp == 2) iti[l] = itseq[n0+l];
  else if (grp == 3) uti[l] = utseq[n0+l];
  else if (grp == 4) nhi[l] = nhseq[n0+l];
  else               nai[l] = naseq[n0+l];
  __syncthreads();

  int sub = tid/48, c4 = tid%48;
  float4 s3v = ((const float4*)g_s3)[c4];
  float4 c0v = ((const float4*)g_c0)[c4];
  const float4* TQ4  = (const float4*)g_TQ;
  const float4* Tit4 = (const float4*)g_Tit;
  const float4* Tut4 = (const float4*)g_Tut;
  const float4* Tnh4 = (const float4*)g_Tnh;
  const float4* Tna4 = (const float4*)g_Tna;

  for (int tl = sub; tl < 32; tl += 4) {
    int n = n0 + tl;
    float4 v  = TQ4 [(size_t)qi[tl]*48 + c4];
    float4 a  = Tit4[iti[tl]*48 + c4];
    float4 bu = Tut4[uti[tl]*48 + c4];
    float4 bh = Tnh4[nhi[tl]*48 + c4];
    float4 ba = Tna4[nai[tl]*48 + c4];
    float cr = cri[tl];
    float4 o;
    o.x = v.x + a.x + bu.x + bh.x + ba.x + cr*s3v.x + c0v.x;
    o.y = v.y + a.y + bu.y + bh.y + ba.y + cr*s3v.y + c0v.y;
    o.z = v.z + a.z + bu.z + bh.z + ba.z + cr*s3v.z + c0v.z;
    o.w = v.w + a.w + bu.w + bh.w + ba.w + cr*s3v.w + c0v.w;
    ((float4*)g_XP)[(size_t)n*48 + c4] = o;
  }
}

// ---------------- K4: GRU scan (low-reg, double-buffered xp) ----------------
__global__ void __launch_bounds__(192, 4) gru_kernel(const float* __restrict__ W_hh,
                                                     const float* __restrict__ b_hh)
{
  __shared__ __align__(16) float h_s[64];
  __shared__ float gh_s[192];
  __shared__ float xp_s[2][192];
  int r = threadIdx.x;
  int b = blockIdx.x;
  ull w2[32];
  const ull* wrow = (const ull*)W_hh + (size_t)r*32;
  #pragma unroll
  for (int i = 0; i < 32; i++) w2[i] = wrow[i];
  float bv = b_hh[r];
  if (r < 64) h_s[r] = 0.f;
  const float* xp = g_XP + (size_t)b*TT*192;
  float* hs = g_HS + (size_t)b*TT*64;
  xp_s[0][r] = xp[r];
  __syncthreads();

  for (int t = 0; t < TT; t++) {
    // next-step xp load in flight during the matvec
    float xph = xp[(size_t)((t+1 < TT) ? t+1 : t)*192 + r];
    ull a0=0ull,a1=0ull,a2=0ull,a3=0ull;
    const ulonglong2* h4 = (const ulonglong2*)h_s;
    #pragma unroll
    for (int i = 0; i < 8; i++) {
      ulonglong2 p = h4[2*i], q = h4[2*i+1];
      a0 = ffma2(w2[4*i+0], p.x, a0);
      a1 = ffma2(w2[4*i+1], p.y, a1);
      a2 = ffma2(w2[4*i+2], q.x, a2);
      a3 = ffma2(w2[4*i+3], q.y, a3);
    }
    float s0,s1,s2,s3,s4,s5,s6,s7;
    unpack2(a0,s0,s1); unpack2(a1,s2,s3); unpack2(a2,s4,s5); unpack2(a3,s6,s7);
    gh_s[r] = bv + (((s0+s1)+(s2+s3)) + ((s4+s5)+(s6+s7)));
    xp_s[(t+1)&1][r] = xph;
    __syncthreads();
    if (r < 64) {
      const float* xc = xp_s[t&1];
      float rg = siga(xc[r]     + gh_s[r]);
      float zg = siga(xc[64+r]  + gh_s[64+r]);
      float ng = tanha(fmaf(rg, gh_s[128+r], xc[128+r]));
      float hnew = fmaf(zg, h_s[r] - ng, ng);
      h_s[r] = hnew;
      hs[(size_t)t*64 + r] = hnew;
    }
    __syncthreads();
  }
}

// ---------------- K5+K6 fused: HL + readout (512 thr, 4 pairs/warp) ---------
__global__ void __launch_bounds__(512, 1) fout_kernel(
                            const float* __restrict__ la_W1, const float* __restrict__ la_b1,
                            const float* __restrict__ la_W2, const float* __restrict__ la_b2,
                            const int* __restrict__ qseq, float* __restrict__ out)
{
  extern __shared__ __align__(16) char sm_[];
  float* Ws = (float*)sm_;                 // [k*132 + row], 64*132 floats
  float* bs = Ws + 64*132;                 // 132 floats (+2 pad)
  ull*   tp = (ull*)(bs + 134);            // [pair*66 + k], 64 pairs

  int tid = threadIdx.x, lane = tid & 31, wid = tid >> 5;
  int n0 = blockIdx.x * 128;

  for (int i = tid; i < 132*64; i += 512) {
    int row = i >> 6, k = i & 63;
    Ws[k*132 + row] = la_W1[i];
  }
  if (tid < 132) bs[tid] = la_b1[tid];
  for (int i = tid; i < 128*16; i += 512) {
    int tok = i >> 4, c = i & 15;
    float4 v = ((const float4*)(g_HS + (size_t)(n0+tok)*64))[c];
    int p = tok >> 1, e = tok & 1;
    float* base = (float*)&tp[p*66 + 4*c];
    base[0+e] = v.x; base[2+e] = v.y; base[4+e] = v.z; base[6+e] = v.w;
  }
  __syncthreads();

  float b0 = bs[lane], b1v = bs[32+lane], b2v = bs[64+lane], b3v = bs[96+lane];
  float b4v = (lane < 4) ? bs[128+lane] : 0.f;
  ull acc[4][5];
  {
    ull p0=pack2(b0,b0), p1=pack2(b1v,b1v), p2=pack2(b2v,b2v), p3=pack2(b3v,b3v), p4=pack2(b4v,b4v);
    #pragma unroll
    for (int p = 0; p < 4; p++) { acc[p][0]=p0; acc[p][1]=p1; acc[p][2]=p2; acc[p][3]=p3; acc[p][4]=p4; }
  }
  int pbase = wid*4;
  #pragma unroll 4
  for (int k = 0; k < 64; k++) {
    float w0 = Ws[k*132 + lane];
    float w1 = Ws[k*132 + 32 + lane];
    float w2v = Ws[k*132 + 64 + lane];
    float w3 = Ws[k*132 + 96 + lane];
    float w4 = (lane < 4) ? Ws[k*132 + 128 + lane] : 0.f;
    ull d0=pack2(w0,w0), d1=pack2(w1,w1), d2=pack2(w2v,w2v), d3=pack2(w3,w3), d4=pack2(w4,w4);
    #pragma unroll
    for (int p = 0; p < 4; p++) {
      ull hd = tp[(pbase+p)*66 + k];
      acc[p][0] = ffma2(d0, hd, acc[p][0]);
      acc[p][1] = ffma2(d1, hd, acc[p][1]);
      acc[p][2] = ffma2(d2, hd, acc[p][2]);
      acc[p][3] = ffma2(d3, hd, acc[p][3]);
      acc[p][4] = ffma2(d4, hd, acc[p][4]);
    }
  }

  #pragma unroll
  for (int p = 0; p < 4; p++) {
    float va[5], vb[5];
    #pragma unroll
    for (int c = 0; c < 5; c++) {
      unpack2(acc[p][c], va[c], vb[c]);
      va[c] = fmaxf(va[c], 0.f);
      vb[c] = fmaxf(vb[c], 0.f);
    }
    #pragma unroll
    for (int e = 0; e < 2; e++) {
      int n = n0 + (pbase + p)*2 + e;
      int bb = n / TT, it = n - bb*TT;
      if (it == TT-1) continue;
      float v0 = e ? vb[0] : va[0];
      float v1 = e ? vb[1] : va[1];
      float v2 = e ? vb[2] : va[2];
      float v3 = e ? vb[3] : va[3];
      float v4 = e ? vb[4] : va[4];

      int q = qseq[n+1];
      int4 c4 = g_qcls[q];
      int carr[4] = {c4.x, c4.y, c4.z, c4.w};
      float S = 0.f;
      #pragma unroll
      for (int jj = 0; jj < 4; jj++) {
        int c = carr[jj];
        if (c < 0) continue;
        const float* w2r = la_W2 + (size_t)c*MIDQ;
        float a = v0*w2r[lane] + v1*w2r[32+lane] + v2*w2r[64+lane] + v3*w2r[96+lane];
        if (lane < 4) a += v4*w2r[128+lane];
        #pragma unroll
        for (int o = 16; o > 0; o >>= 1) a += __shfl_xor_sync(0xffffffffu, a, o);
        if (lane == 0) S += fsig(a + la_b2[c]);
      }
      if (lane == 0) {
        float sq = g_qSqd[q];
        float y = g_qdisc[q]*__fdividef(S - sq, sq + 1e-6f);
        out[bb*(TT-1) + it] = fsig(y);
      }
    }
  }
}

// ---------------- launcher --------------------------------------------------
extern "C" void kernel_launch(void* const* d_in, const int* in_sizes, int n_in,
                              void* d_out, int out_size)
{
  const float* E_q    = (const float*)d_in[0];
  const float* E_c    = (const float*)d_in[1];
  const float* E_it   = (const float*)d_in[2];
  const float* E_ut   = (const float*)d_in[3];
  const float* E_nh   = (const float*)d_in[4];
  const float* W_fuse = (const float*)d_in[5];
  const float* b_fuse = (const float*)d_in[6];
  const float* W_ih   = (const float*)d_in[7];
  const float* b_ih   = (const float*)d_in[8];
  const float* W_hh   = (const float*)d_in[9];
  const float* b_hh   = (const float*)d_in[10];
  const float* qd_W1  = (const float*)d_in[11];
  const float* qd_b1  = (const float*)d_in[12];
  const float* qd_W2  = (const float*)d_in[13];
  const float* qd_b2  = (const float*)d_in[14];
  const float* la_W1  = (const float*)d_in[15];
  const float* la_b1  = (const float*)d_in[16];
  const float* la_W2  = (const float*)d_in[17];
  const float* la_b2  = (const float*)d_in[18];
  const float* dc_W1  = (const float*)d_in[19];
  const float* dc_b1  = (const float*)d_in[20];
  const float* dc_W2  = (const float*)d_in[21];
  const float* dc_b2  = (const float*)d_in[22];

  int off = (in_sizes[23] > 1000000) ? 1 : 0;
  const int* qseq  = (const int*)d_in[23+off];
  const int* cseq  = (const int*)d_in[24+off];
  const int* itseq = (const int*)d_in[25+off];
  const int* utseq = (const int*)d_in[26+off];
  const int* nhseq = (const int*)d_in[27+off];
  const int* naseq = (const int*)d_in[28+off];
  const int* q2c   = (const int*)d_in[29+off];
  const int* q2cm  = (const int*)d_in[30+off];

  const int P0_SMEM = 33024;                          // max(tq 33024, hq 32768)
  const int FOUT_SMEM = (64*132 + 134)*4 + 64*66*8;   // 68120 bytes
  cudaFuncSetAttribute(fout_kernel, cudaFuncAttributeMaxDynamicSharedMemorySize, FOUT_SMEM);

  p0_kernel<<<842, 256, P0_SMEM>>>(E_q, E_c, E_it, E_ut, E_nh,
                                   W_ih, b_ih, W_fuse, b_fuse, qd_W1, qd_b1);
  p1b_kernel<<<(NQ+7)/8, 256>>>(E_q, qd_W2, qd_b2, dc_W1, dc_b1, dc_W2, dc_b2, q2c, q2cm);
  xp_kernel<<<NTOK/32, 192>>>(qseq, cseq, itseq, utseq, nhseq, naseq);
  gru_kernel<<<BB, 192>>>(W_hh, b_hh);           // launch #4 -> profiled
  fout_kernel<<<NTOK/128, 512, FOUT_SMEM>>>(la_W1, la_b1, la_W2, la_b2, qseq, (float*)d_out);
}